// round 2
// baseline (speedup 1.0000x reference)
#include <cuda_runtime.h>
#include <math.h>

// Problem constants (fixed shapes)
#define TTOK 4096
#define HDIM 1024
#define IDIM 2048
#define NE   8
#define NPAIR (TTOK * 2)

// GEMM tile config
#define BM 128
#define BN 64
#define BK 8
#define NTHR 256
#define AS_STRIDE (BM + 4)   // pads away smem bank conflicts
#define BS_STRIDE (BN + 4)
#define ROWT 32              // max row tiles per expert = TTOK/BM

// ---------------- scratch (static __device__ — no allocation) ----------------
__device__ float g_act[(size_t)NPAIR * IDIM];          // routed swiglu activations (64 MiB)
__device__ float g_acts[(size_t)TTOK * IDIM];          // shared swiglu activations (32 MiB)
__device__ float g_partial[2][(size_t)TTOK * HDIM];    // per-slot down outputs     (32 MiB)
__device__ int   g_row_tok[NPAIR];
__device__ float g_row_sc[NPAIR];
__device__ int   g_row_slot[NPAIR];
__device__ int   g_tope[NPAIR];
__device__ float g_tops[NPAIR];
__device__ int   g_cnt[NE];
__device__ int   g_off[NE];
__device__ int   g_cur[NE];

// ---------------- tiny control kernels ----------------
__global__ void k_init() {
    if (threadIdx.x < NE) g_cnt[threadIdx.x] = 0;
}

__global__ void k_prefix() {
    if (threadIdx.x == 0) {
        int s = 0;
        for (int e = 0; e < NE; e++) { g_off[e] = s; s += g_cnt[e]; }
    }
    if (threadIdx.x < NE) g_cur[threadIdx.x] = 0;
}

// ---------------- router: logits + top2 + sigmoid + counts ----------------
__global__ __launch_bounds__(128) void k_router(const float* __restrict__ x,
                                                const float* __restrict__ rw,
                                                float* __restrict__ out_logits) {
    int warp = threadIdx.x >> 5, lane = threadIdx.x & 31;
    int t = blockIdx.x * 4 + warp;
    if (t >= TTOK) return;
    const float* xr = x + (size_t)t * HDIM;
    float acc[NE];
#pragma unroll
    for (int e = 0; e < NE; e++) acc[e] = 0.f;
    for (int i = lane; i < HDIM; i += 32) {
        float xv = xr[i];
#pragma unroll
        for (int e = 0; e < NE; e++) acc[e] = fmaf(xv, rw[e * HDIM + i], acc[e]);
    }
#pragma unroll
    for (int e = 0; e < NE; e++) {
#pragma unroll
        for (int o = 16; o > 0; o >>= 1) acc[e] += __shfl_xor_sync(0xFFFFFFFFu, acc[e], o);
    }
    if (lane == 0) {
        if (out_logits) {
#pragma unroll
            for (int e = 0; e < NE; e++) out_logits[(size_t)t * NE + e] = acc[e];
        }
        // top-2: strict > keeps lowest index on ties (matches lax.top_k)
        int e1 = 0; float v1 = acc[0];
#pragma unroll
        for (int e = 1; e < NE; e++) if (acc[e] > v1) { v1 = acc[e]; e1 = e; }
        int e2 = -1; float v2 = -1e30f;
#pragma unroll
        for (int e = 0; e < NE; e++) if (e != e1 && acc[e] > v2) { v2 = acc[e]; e2 = e; }
        float s1 = 1.f / (1.f + __expf(-v1));
        float s2 = 1.f / (1.f + __expf(-v2));
        g_tope[t * 2 + 0] = e1; g_tops[t * 2 + 0] = s1;
        g_tope[t * 2 + 1] = e2; g_tops[t * 2 + 1] = s2;
        atomicAdd(&g_cnt[e1], 1);
        atomicAdd(&g_cnt[e2], 1);
    }
}

// ---------------- scatter tokens into per-expert contiguous rows ----------------
__global__ __launch_bounds__(256) void k_scatter() {
    __shared__ int lcnt[NE], lbase[NE];
    int tid = threadIdx.x;
    if (tid < NE) lcnt[tid] = 0;
    __syncthreads();
    int t = blockIdx.x * 256 + tid;
    int e0 = g_tope[2 * t], e1 = g_tope[2 * t + 1];
    float s0 = g_tops[2 * t], s1 = g_tops[2 * t + 1];
    int p0 = atomicAdd(&lcnt[e0], 1);
    int p1 = atomicAdd(&lcnt[e1], 1);
    __syncthreads();
    if (tid < NE) lbase[tid] = atomicAdd(&g_cur[tid], lcnt[tid]);
    __syncthreads();
    int r0 = g_off[e0] + lbase[e0] + p0;
    int r1 = g_off[e1] + lbase[e1] + p1;
    g_row_tok[r0] = t; g_row_sc[r0] = s0; g_row_slot[r0] = 0;
    g_row_tok[r1] = t; g_row_sc[r1] = s1; g_row_slot[r1] = 1;
}

// ---------------- GEMM micro-kernel ----------------
__device__ __forceinline__ void micro_fma(float acc[8][4], const float* As,
                                          const float* Bs, int ty, int tx) {
#pragma unroll
    for (int kk = 0; kk < BK; kk++) {
        float4 a0 = *(const float4*)&As[kk * AS_STRIDE + ty * 8];
        float4 a1 = *(const float4*)&As[kk * AS_STRIDE + ty * 8 + 4];
        float4 b  = *(const float4*)&Bs[kk * BS_STRIDE + tx * 4];
        float a[8] = {a0.x, a0.y, a0.z, a0.w, a1.x, a1.y, a1.z, a1.w};
        float bb[4] = {b.x, b.y, b.z, b.w};
#pragma unroll
        for (int m = 0; m < 8; m++)
#pragma unroll
            for (int n = 0; n < 4; n++)
                acc[m][n] = fmaf(a[m], bb[n], acc[m][n]);
    }
}

__device__ __forceinline__ float silu_mul(float g, float u) {
    return u * g / (1.f + __expf(-g));
}

// ---------------- routed gate_up + SwiGLU: act[row, I] ----------------
// Each block: A tile [BM x K] shared between gate B tile and up B tile.
__global__ __launch_bounds__(NTHR) void k_gateup_routed(const float* __restrict__ x,
                                                        const float* __restrict__ gup) {
    int e = blockIdx.y >> 5;
    int rt = blockIdx.y & 31;
    int cnt = g_cnt[e];
    int row0 = rt * BM;
    if (row0 >= cnt) return;
    int base = g_off[e];

    __shared__ float As[BK * AS_STRIDE];
    __shared__ float Bg[BK * BS_STRIDE];
    __shared__ float Bu[BK * BS_STRIDE];
    __shared__ int   s_tok[BM];
    __shared__ float s_sc[BM];

    int tid = threadIdx.x;
    for (int i = tid; i < BM; i += NTHR) {
        int r = min(row0 + i, cnt - 1);
        s_tok[i] = g_row_tok[base + r];
        s_sc[i]  = g_row_sc[base + r];
    }
    __syncthreads();

    int tx = tid & 15, ty = tid >> 4;
    int j0 = blockIdx.x * BN;
    const float* Bgp = gup + (size_t)e * HDIM * (2 * IDIM) + j0;
    const float* Bup = Bgp + IDIM;

    int ar = tid >> 1, aseg = (tid & 1) * 4;
    const float* xrow = x + (size_t)s_tok[ar] * HDIM + aseg;
    float scA = s_sc[ar];
    int bk = tid >> 5, bj = (tid & 31) * 2;

    float accg[8][4], accu[8][4];
#pragma unroll
    for (int m = 0; m < 8; m++)
#pragma unroll
        for (int n = 0; n < 4; n++) { accg[m][n] = 0.f; accu[m][n] = 0.f; }

    for (int k0 = 0; k0 < HDIM; k0 += BK) {
        float4 av = *(const float4*)&xrow[k0];
        As[(aseg + 0) * AS_STRIDE + ar] = av.x * scA;
        As[(aseg + 1) * AS_STRIDE + ar] = av.y * scA;
        As[(aseg + 2) * AS_STRIDE + ar] = av.z * scA;
        As[(aseg + 3) * AS_STRIDE + ar] = av.w * scA;
        float2 bg = *(const float2*)&Bgp[(size_t)(k0 + bk) * (2 * IDIM) + bj];
        float2 bu = *(const float2*)&Bup[(size_t)(k0 + bk) * (2 * IDIM) + bj];
        Bg[bk * BS_STRIDE + bj]     = bg.x;
        Bg[bk * BS_STRIDE + bj + 1] = bg.y;
        Bu[bk * BS_STRIDE + bj]     = bu.x;
        Bu[bk * BS_STRIDE + bj + 1] = bu.y;
        __syncthreads();
        micro_fma(accg, As, Bg, ty, tx);
        micro_fma(accu, As, Bu, ty, tx);
        __syncthreads();
    }

#pragma unroll
    for (int m = 0; m < 8; m++) {
        int r = ty * 8 + m;
        if (row0 + r < cnt) {
            int grow = base + row0 + r;
            float4 v;
            v.x = silu_mul(accg[m][0], accu[m][0]);
            v.y = silu_mul(accg[m][1], accu[m][1]);
            v.z = silu_mul(accg[m][2], accu[m][2]);
            v.w = silu_mul(accg[m][3], accu[m][3]);
            *(float4*)&g_act[(size_t)grow * IDIM + j0 + tx * 4] = v;
        }
    }
}

// ---------------- routed down: partial[slot][tok] = act @ down[e] ----------------
__global__ __launch_bounds__(NTHR) void k_down_routed(const float* __restrict__ dwn) {
    int e = blockIdx.y >> 5;
    int rt = blockIdx.y & 31;
    int cnt = g_cnt[e];
    int row0 = rt * BM;
    if (row0 >= cnt) return;
    int base = g_off[e];

    __shared__ float As[BK * AS_STRIDE];
    __shared__ float Bs[BK * BS_STRIDE];
    __shared__ int   s_tok[BM];
    __shared__ int   s_slot[BM];

    int tid = threadIdx.x;
    for (int i = tid; i < BM; i += NTHR) {
        int r = min(row0 + i, cnt - 1);
        s_tok[i]  = g_row_tok[base + r];
        s_slot[i] = g_row_slot[base + r];
    }
    __syncthreads();

    int tx = tid & 15, ty = tid >> 4;
    int j0 = blockIdx.x * BN;
    const float* B = dwn + (size_t)e * IDIM * HDIM + j0;

    int ar = tid >> 1, aseg = (tid & 1) * 4;
    int grow_a = base + min(row0 + ar, cnt - 1);
    const float* arow = &g_act[(size_t)grow_a * IDIM + aseg];
    int bk = tid >> 5, bj = (tid & 31) * 2;

    float acc[8][4];
#pragma unroll
    for (int m = 0; m < 8; m++)
#pragma unroll
        for (int n = 0; n < 4; n++) acc[m][n] = 0.f;

    for (int k0 = 0; k0 < IDIM; k0 += BK) {
        float4 av = *(const float4*)&arow[k0];
        As[(aseg + 0) * AS_STRIDE + ar] = av.x;
        As[(aseg + 1) * AS_STRIDE + ar] = av.y;
        As[(aseg + 2) * AS_STRIDE + ar] = av.z;
        As[(aseg + 3) * AS_STRIDE + ar] = av.w;
        float2 bv = *(const float2*)&B[(size_t)(k0 + bk) * HDIM + bj];
        Bs[bk * BS_STRIDE + bj]     = bv.x;
        Bs[bk * BS_STRIDE + bj + 1] = bv.y;
        __syncthreads();
        micro_fma(acc, As, Bs, ty, tx);
        __syncthreads();
    }

#pragma unroll
    for (int m = 0; m < 8; m++) {
        int r = ty * 8 + m;
        if (row0 + r < cnt) {
            int tok = s_tok[r], slot = s_slot[r];
            float4 v = {acc[m][0], acc[m][1], acc[m][2], acc[m][3]};
            *(float4*)&g_partial[slot][(size_t)tok * HDIM + j0 + tx * 4] = v;
        }
    }
}

// ---------------- shared gate/up + SwiGLU: acts[t, I] ----------------
__global__ __launch_bounds__(NTHR) void k_gateup_shared(const float* __restrict__ x,
                                                        const float* __restrict__ gate_w,
                                                        const float* __restrict__ up_w) {
    int row0 = blockIdx.y * BM;
    int j0 = blockIdx.x * BN;

    __shared__ float As[BK * AS_STRIDE];
    __shared__ float Bg[BK * BS_STRIDE];
    __shared__ float Bu[BK * BS_STRIDE];

    int tid = threadIdx.x;
    int tx = tid & 15, ty = tid >> 4;
    int ar = tid >> 1, aseg = (tid & 1) * 4;
    const float* xrow = x + (size_t)(row0 + ar) * HDIM + aseg;
    int kk2 = (2 * tid) & 7, jB = (2 * tid) >> 3;

    float accg[8][4], accu[8][4];
#pragma unroll
    for (int m = 0; m < 8; m++)
#pragma unroll
        for (int n = 0; n < 4; n++) { accg[m][n] = 0.f; accu[m][n] = 0.f; }

    for (int k0 = 0; k0 < HDIM; k0 += BK) {
        float4 av = *(const float4*)&xrow[k0];
        As[(aseg + 0) * AS_STRIDE + ar] = av.x;
        As[(aseg + 1) * AS_STRIDE + ar] = av.y;
        As[(aseg + 2) * AS_STRIDE + ar] = av.z;
        As[(aseg + 3) * AS_STRIDE + ar] = av.w;
        float2 wg = *(const float2*)&gate_w[(size_t)(j0 + jB) * HDIM + k0 + kk2];
        float2 wu = *(const float2*)&up_w[(size_t)(j0 + jB) * HDIM + k0 + kk2];
        Bg[kk2 * BS_STRIDE + jB]       = wg.x;
        Bg[(kk2 + 1) * BS_STRIDE + jB] = wg.y;
        Bu[kk2 * BS_STRIDE + jB]       = wu.x;
        Bu[(kk2 + 1) * BS_STRIDE + jB] = wu.y;
        __syncthreads();
        micro_fma(accg, As, Bg, ty, tx);
        micro_fma(accu, As, Bu, ty, tx);
        __syncthreads();
    }

#pragma unroll
    for (int m = 0; m < 8; m++) {
        int r = ty * 8 + m;
        float4 v;
        v.x = silu_mul(accg[m][0], accu[m][0]);
        v.y = silu_mul(accg[m][1], accu[m][1]);
        v.z = silu_mul(accg[m][2], accu[m][2]);
        v.w = silu_mul(accg[m][3], accu[m][3]);
        *(float4*)&g_acts[(size_t)(row0 + r) * IDIM + j0 + tx * 4] = v;
    }
}

// ---------------- shared down + final add: out = acts@Wd^T + p0 + p1 ----------------
__global__ __launch_bounds__(NTHR) void k_down_shared(const float* __restrict__ down_w,
                                                      float* __restrict__ out) {
    int row0 = blockIdx.y * BM;
    int j0 = blockIdx.x * BN;

    __shared__ float As[BK * AS_STRIDE];
    __shared__ float Bs[BK * BS_STRIDE];

    int tid = threadIdx.x;
    int tx = tid & 15, ty = tid >> 4;
    int ar = tid >> 1, aseg = (tid & 1) * 4;
    const float* arow = &g_acts[(size_t)(row0 + ar) * IDIM + aseg];
    int kk2 = (2 * tid) & 7, jB = (2 * tid) >> 3;

    float acc[8][4];
#pragma unroll
    for (int m = 0; m < 8; m++)
#pragma unroll
        for (int n = 0; n < 4; n++) acc[m][n] = 0.f;

    for (int k0 = 0; k0 < IDIM; k0 += BK) {
        float4 av = *(const float4*)&arow[k0];
        As[(aseg + 0) * AS_STRIDE + ar] = av.x;
        As[(aseg + 1) * AS_STRIDE + ar] = av.y;
        As[(aseg + 2) * AS_STRIDE + ar] = av.z;
        As[(aseg + 3) * AS_STRIDE + ar] = av.w;
        float2 wv = *(const float2*)&down_w[(size_t)(j0 + jB) * IDIM + k0 + kk2];
        Bs[kk2 * BS_STRIDE + jB]       = wv.x;
        Bs[(kk2 + 1) * BS_STRIDE + jB] = wv.y;
        __syncthreads();
        micro_fma(acc, As, Bs, ty, tx);
        __syncthreads();
    }

#pragma unroll
    for (int m = 0; m < 8; m++) {
        int r = ty * 8 + m;
        size_t idx = (size_t)(row0 + r) * HDIM + j0 + tx * 4;
        float4 p0 = *(const float4*)&g_partial[0][idx];
        float4 p1 = *(const float4*)&g_partial[1][idx];
        float4 v;
        v.x = acc[m][0] + p0.x + p1.x;
        v.y = acc[m][1] + p0.y + p1.y;
        v.z = acc[m][2] + p0.z + p1.z;
        v.w = acc[m][3] + p0.w + p1.w;
        *(float4*)&out[idx] = v;
    }
}

// ---------------- launch ----------------
extern "C" void kernel_launch(void* const* d_in, const int* in_sizes, int n_in,
                              void* d_out, int out_size) {
    const float* x       = (const float*)d_in[0];   // [T, H]
    const float* rw      = (const float*)d_in[1];   // [E, H]
    const float* gup     = (const float*)d_in[2];   // [E, H, 2I]
    const float* dwn     = (const float*)d_in[3];   // [E, I, H]
    const float* sgate   = (const float*)d_in[4];   // [I, H]
    const float* sup     = (const float*)d_in[5];   // [I, H]
    const float* sdown   = (const float*)d_in[6];   // [H, I]
    float* out = (float*)d_out;

    float* out_logits = nullptr;
    if (out_size >= TTOK * HDIM + TTOK * NE) out_logits = out + (size_t)TTOK * HDIM;

    k_init<<<1, 32>>>();
    k_router<<<TTOK / 4, 128>>>(x, rw, out_logits);
    k_prefix<<<1, 32>>>();
    k_scatter<<<TTOK / 256, 256>>>();
    k_gateup_routed<<<dim3(IDIM / BN, NE * ROWT), NTHR>>>(x, gup);
    k_down_routed<<<dim3(HDIM / BN, NE * ROWT), NTHR>>>(dwn);
    k_gateup_shared<<<dim3(IDIM / BN, TTOK / BM), NTHR>>>(x, sgate, sup);
    k_down_shared<<<dim3(HDIM / BN, TTOK / BM), NTHR>>>(sdown, out);
}

// round 5
// speedup vs baseline: 1.7416x; 1.7416x over previous
#include <cuda_runtime.h>
#include <cuda_bf16.h>
#include <stdint.h>
#include <math.h>

// Problem constants
#define TTOK 4096
#define HDIM 1024
#define IDIM 2048
#define NE   8
#define NPAIR (TTOK * 2)

// GEMM config: 128x128 CTA tile, 8 warps (4M x 2N), KC=32, double-buffered
#define KC 32
#define A_PITCH 80               // bytes per smem row (40 bf16, conflict-free frag loads)
#define SM_AH 0
#define SM_AL 10240
#define SM_BH 20480
#define SM_BL 30720
#define SM_STAGE 40960
#define SMEM_GEMM (2 * SM_STAGE) // 81920 B

// ---------------- scratch (static __device__ — no allocation) ----------------
__device__ float g_act[(size_t)NPAIR * IDIM];          // routed swiglu activations
__device__ float g_acts[(size_t)TTOK * IDIM];          // shared swiglu activations
__device__ float g_partial[2][(size_t)TTOK * HDIM];    // per-slot routed outputs
__device__ int   g_row_tok[NPAIR];
__device__ float g_row_sc[NPAIR];
__device__ int   g_row_slot[NPAIR];
__device__ int   g_tope[NPAIR];
__device__ float g_tops[NPAIR];
__device__ int   g_cnt[NE];
__device__ int   g_off[NE];
__device__ int   g_cur[NE];

// bf16 hi/lo weights, [n][k] col-major-for-mma layouts
__device__ __nv_bfloat16 g_wgu_h[(size_t)NE * 2 * IDIM * HDIM];  // interleaved gate/up rows
__device__ __nv_bfloat16 g_wgu_l[(size_t)NE * 2 * IDIM * HDIM];
__device__ __nv_bfloat16 g_wdn_h[(size_t)NE * HDIM * IDIM];      // [H][I]
__device__ __nv_bfloat16 g_wdn_l[(size_t)NE * HDIM * IDIM];
__device__ __nv_bfloat16 g_wsg_h[(size_t)2 * IDIM * HDIM];       // shared gate/up interleaved
__device__ __nv_bfloat16 g_wsg_l[(size_t)2 * IDIM * HDIM];
__device__ __nv_bfloat16 g_wsd_h[(size_t)HDIM * IDIM];           // [H][I]
__device__ __nv_bfloat16 g_wsd_l[(size_t)HDIM * IDIM];

// ---------------- small helpers ----------------
__device__ __forceinline__ uint32_t smem_u32(const void* p) {
    uint32_t a;
    asm("{ .reg .u64 t; cvta.to.shared.u64 t, %1; cvt.u32.u64 %0, t; }" : "=r"(a) : "l"(p));
    return a;
}
__device__ __forceinline__ void cpa16(uint32_t saddr, const void* g) {
    asm volatile("cp.async.ca.shared.global [%0], [%1], 16;" :: "r"(saddr), "l"(g));
}
__device__ __forceinline__ void cpa_commit() {
    asm volatile("cp.async.commit_group;" ::: "memory");
}
__device__ __forceinline__ void cpa_wait0() {
    asm volatile("cp.async.wait_group 0;" ::: "memory");
}
__device__ __forceinline__ uint32_t packraw(__nv_bfloat16 a, __nv_bfloat16 b) {
    __nv_bfloat162 t(a, b);
    return *reinterpret_cast<uint32_t*>(&t);
}
__device__ __forceinline__ uint32_t packbf2(float a, float b) {
    __nv_bfloat162 t = __floats2bfloat162_rn(a, b);
    return *reinterpret_cast<uint32_t*>(&t);
}
__device__ __forceinline__ float silu_mul(float g, float u) {
    return u * g / (1.f + __expf(-g));
}
__device__ __forceinline__ void mma16816(float d[4], uint32_t a0, uint32_t a1, uint32_t a2,
                                         uint32_t a3, uint32_t b0, uint32_t b1) {
    asm volatile(
        "mma.sync.aligned.m16n8k16.row.col.f32.bf16.bf16.f32 "
        "{%0,%1,%2,%3}, {%4,%5,%6,%7}, {%8,%9}, {%0,%1,%2,%3};"
        : "+f"(d[0]), "+f"(d[1]), "+f"(d[2]), "+f"(d[3])
        : "r"(a0), "r"(a1), "r"(a2), "r"(a3), "r"(b0), "r"(b1));
}

// ---------------- GEMM core: C[128x128] += A(fp32, split) * B(bf16 hi/lo, [n][k]) ----------------
__device__ __forceinline__ void gemm_core(const float* __restrict__ aptr, float asc,
                                          const __nv_bfloat16* __restrict__ Bh,
                                          const __nv_bfloat16* __restrict__ Bl,
                                          int Ktot, char* sm, uint32_t sbu,
                                          float acc[2][8][4]) {
    const int t = threadIdx.x;
    const int lane = t & 31, wid = t >> 5;
    const int g = lane >> 2, tg = lane & 3;
    const int wm0 = (wid >> 1) * 32, wn0 = (wid & 1) * 64;
    const int rb = t >> 1, half = t & 1;
    const int nc = Ktot / KC;

    const float* ap = aptr + half * 16;
    const __nv_bfloat16* bhp = Bh + (size_t)rb * Ktot + half * 16;
    const __nv_bfloat16* blp = Bl + (size_t)rb * Ktot + half * 16;
    const uint32_t sBh = sbu + SM_BH + rb * A_PITCH + half * 32;
    const uint32_t sBl = sbu + SM_BL + rb * A_PITCH + half * 32;

    float av[16];

    // prologue: chunk 0
    {
        const float4* p = (const float4*)ap;
#pragma unroll
        for (int i = 0; i < 4; i++) {
            float4 v = p[i];
            av[i * 4 + 0] = v.x; av[i * 4 + 1] = v.y;
            av[i * 4 + 2] = v.z; av[i * 4 + 3] = v.w;
        }
        cpa16(sBh, bhp); cpa16(sBh + 16, bhp + 8);
        cpa16(sBl, blp); cpa16(sBl + 16, blp + 8);
        cpa_commit();
        char* dh = sm + SM_AH + rb * A_PITCH + half * 32;
        char* dl = sm + SM_AL + rb * A_PITCH + half * 32;
#pragma unroll
        for (int i = 0; i < 8; i++) {
            float x0 = av[2 * i] * asc, x1 = av[2 * i + 1] * asc;
            __nv_bfloat16 h0 = __float2bfloat16_rn(x0), h1 = __float2bfloat16_rn(x1);
            *(uint32_t*)(dh + i * 4) = packraw(h0, h1);
            *(uint32_t*)(dl + i * 4) =
                packbf2(x0 - __bfloat162float(h0), x1 - __bfloat162float(h1));
        }
    }

    for (int c = 0; c < nc; c++) {
        const int s = c & 1;
        cpa_wait0();
        __syncthreads();
        const bool more = (c + 1 < nc);
        if (more) {
            const float4* p = (const float4*)(ap + (c + 1) * KC);
#pragma unroll
            for (int i = 0; i < 4; i++) {
                float4 v = p[i];
                av[i * 4 + 0] = v.x; av[i * 4 + 1] = v.y;
                av[i * 4 + 2] = v.z; av[i * 4 + 3] = v.w;
            }
            const uint32_t so = (1 - s) * SM_STAGE;
            const __nv_bfloat16* ph = bhp + (c + 1) * KC;
            const __nv_bfloat16* pl = blp + (c + 1) * KC;
            cpa16(sBh + so, ph); cpa16(sBh + so + 16, ph + 8);
            cpa16(sBl + so, pl); cpa16(sBl + so + 16, pl + 8);
            cpa_commit();
        }
        // MMA on stage s
        {
            const char* sA_h = sm + s * SM_STAGE + SM_AH;
            const char* sA_l = sm + s * SM_STAGE + SM_AL;
            const char* sB_h = sm + s * SM_STAGE + SM_BH;
            const char* sB_l = sm + s * SM_STAGE + SM_BL;
#pragma unroll
            for (int ks = 0; ks < 2; ks++) {
                uint32_t ah[2][4], al[2][4];
#pragma unroll
                for (int mi = 0; mi < 2; mi++) {
                    int rbase = (wm0 + mi * 16 + g) * A_PITCH + ks * 32 + tg * 4;
                    ah[mi][0] = *(const uint32_t*)(sA_h + rbase);
                    ah[mi][1] = *(const uint32_t*)(sA_h + rbase + 8 * A_PITCH);
                    ah[mi][2] = *(const uint32_t*)(sA_h + rbase + 16);
                    ah[mi][3] = *(const uint32_t*)(sA_h + rbase + 8 * A_PITCH + 16);
                    al[mi][0] = *(const uint32_t*)(sA_l + rbase);
                    al[mi][1] = *(const uint32_t*)(sA_l + rbase + 8 * A_PITCH);
                    al[mi][2] = *(const uint32_t*)(sA_l + rbase + 16);
                    al[mi][3] = *(const uint32_t*)(sA_l + rbase + 8 * A_PITCH + 16);
                }
#pragma unroll
                for (int nj = 0; nj < 8; nj++) {
                    int nb = (wn0 + nj * 8 + g) * A_PITCH + ks * 32 + tg * 4;
                    uint32_t bh0 = *(const uint32_t*)(sB_h + nb);
                    uint32_t bh1 = *(const uint32_t*)(sB_h + nb + 16);
                    uint32_t bl0 = *(const uint32_t*)(sB_l + nb);
                    uint32_t bl1 = *(const uint32_t*)(sB_l + nb + 16);
#pragma unroll
                    for (int mi = 0; mi < 2; mi++) {
                        mma16816(acc[mi][nj], ah[mi][0], ah[mi][1], ah[mi][2], ah[mi][3], bh0, bh1);
                        mma16816(acc[mi][nj], ah[mi][0], ah[mi][1], ah[mi][2], ah[mi][3], bl0, bl1);
                        mma16816(acc[mi][nj], al[mi][0], al[mi][1], al[mi][2], al[mi][3], bh0, bh1);
                    }
                }
            }
        }
        if (more) {
            char* dh = sm + (1 - s) * SM_STAGE + SM_AH + rb * A_PITCH + half * 32;
            char* dl = sm + (1 - s) * SM_STAGE + SM_AL + rb * A_PITCH + half * 32;
#pragma unroll
            for (int i = 0; i < 8; i++) {
                float x0 = av[2 * i] * asc, x1 = av[2 * i + 1] * asc;
                __nv_bfloat16 h0 = __float2bfloat16_rn(x0), h1 = __float2bfloat16_rn(x1);
                *(uint32_t*)(dh + i * 4) = packraw(h0, h1);
                *(uint32_t*)(dl + i * 4) =
                    packbf2(x0 - __bfloat162float(h0), x1 - __bfloat162float(h1));
            }
        }
    }
}

// ---------------- weight conversion ----------------
// transpose-convert: src fp32 [K][N] (per-expert) -> dst bf16 hi/lo [n'][K]
__device__ __forceinline__ void cvt_T_body(const float* __restrict__ s,
                                           __nv_bfloat16* __restrict__ oh,
                                           __nv_bfloat16* __restrict__ ol,
                                           int K, int N, int remap_half) {
    __shared__ float tile[32][33];
    int c0 = blockIdx.x * 32;
    int k0 = blockIdx.y * 32;
    int tx = threadIdx.x, ty = threadIdx.y;
#pragma unroll
    for (int i = 0; i < 4; i++) {
        int k = ty + i * 8;
        tile[k][tx] = s[(size_t)(k0 + k) * N + c0 + tx];
    }
    __syncthreads();
#pragma unroll
    for (int i = 0; i < 4; i++) {
        int cc = c0 + ty + i * 8;
        int n = remap_half ? (2 * (cc % remap_half) + cc / remap_half) : cc;
        float v = tile[tx][ty + i * 8];
        __nv_bfloat16 h = __float2bfloat16_rn(v);
        oh[(size_t)n * K + k0 + tx] = h;
        ol[(size_t)n * K + k0 + tx] = __float2bfloat16_rn(v - __bfloat162float(h));
    }
}

__global__ void k_cvt_gup(const float* __restrict__ gup) {
    int e = blockIdx.z;
    cvt_T_body(gup + (size_t)e * HDIM * 2 * IDIM,
               g_wgu_h + (size_t)e * 2 * IDIM * HDIM,
               g_wgu_l + (size_t)e * 2 * IDIM * HDIM, HDIM, 2 * IDIM, IDIM);
}
__global__ void k_cvt_dwn(const float* __restrict__ dwn) {
    int e = blockIdx.z;
    cvt_T_body(dwn + (size_t)e * IDIM * HDIM,
               g_wdn_h + (size_t)e * HDIM * IDIM,
               g_wdn_l + (size_t)e * HDIM * IDIM, IDIM, HDIM, 0);
}
__global__ void k_cvt_sharedgu(const float* __restrict__ gw, const float* __restrict__ uw) {
    size_t id = (size_t)blockIdx.x * 256 + threadIdx.x;   // over I*H
    int j = (int)(id / HDIM), k = (int)(id % HDIM);
    float gv = gw[id], uv = uw[id];
    __nv_bfloat16 gh = __float2bfloat16_rn(gv), uh = __float2bfloat16_rn(uv);
    size_t rg = (size_t)(2 * j) * HDIM + k, ru = (size_t)(2 * j + 1) * HDIM + k;
    g_wsg_h[rg] = gh; g_wsg_l[rg] = __float2bfloat16_rn(gv - __bfloat162float(gh));
    g_wsg_h[ru] = uh; g_wsg_l[ru] = __float2bfloat16_rn(uv - __bfloat162float(uh));
}
__global__ void k_cvt_shareddn(const float* __restrict__ dw) {
    size_t id = (size_t)blockIdx.x * 256 + threadIdx.x;   // over H*I
    float v = dw[id];
    __nv_bfloat16 h = __float2bfloat16_rn(v);
    g_wsd_h[id] = h; g_wsd_l[id] = __float2bfloat16_rn(v - __bfloat162float(h));
}

// ---------------- tiny control kernels ----------------
__global__ void k_init() { if (threadIdx.x < NE) g_cnt[threadIdx.x] = 0; }
__global__ void k_prefix() {
    if (threadIdx.x == 0) {
        int s = 0;
        for (int e = 0; e < NE; e++) { g_off[e] = s; s += g_cnt[e]; }
    }
    if (threadIdx.x < NE) g_cur[threadIdx.x] = 0;
}

// ---------------- router ----------------
__global__ __launch_bounds__(128) void k_router(const float* __restrict__ x,
                                                const float* __restrict__ rw,
                                                float* __restrict__ out_logits) {
    int warp = threadIdx.x >> 5, lane = threadIdx.x & 31;
    int t = blockIdx.x * 4 + warp;
    if (t >= TTOK) return;
    const float* xr = x + (size_t)t * HDIM;
    float acc[NE];
#pragma unroll
    for (int e = 0; e < NE; e++) acc[e] = 0.f;
    for (int i = lane; i < HDIM; i += 32) {
        float xv = xr[i];
#pragma unroll
        for (int e = 0; e < NE; e++) acc[e] = fmaf(xv, rw[e * HDIM + i], acc[e]);
    }
#pragma unroll
    for (int e = 0; e < NE; e++) {
#pragma unroll
        for (int o = 16; o > 0; o >>= 1) acc[e] += __shfl_xor_sync(0xFFFFFFFFu, acc[e], o);
    }
    if (lane == 0) {
        if (out_logits) {
#pragma unroll
            for (int e = 0; e < NE; e++) out_logits[(size_t)t * NE + e] = acc[e];
        }
        int e1 = 0; float v1 = acc[0];
#pragma unroll
        for (int e = 1; e < NE; e++) if (acc[e] > v1) { v1 = acc[e]; e1 = e; }
        int e2 = -1; float v2 = -1e30f;
#pragma unroll
        for (int e = 0; e < NE; e++) if (e != e1 && acc[e] > v2) { v2 = acc[e]; e2 = e; }
        float s1 = 1.f / (1.f + __expf(-v1));
        float s2 = 1.f / (1.f + __expf(-v2));
        g_tope[t * 2 + 0] = e1; g_tops[t * 2 + 0] = s1;
        g_tope[t * 2 + 1] = e2; g_tops[t * 2 + 1] = s2;
        atomicAdd(&g_cnt[e1], 1);
        atomicAdd(&g_cnt[e2], 1);
    }
}

// ---------------- scatter ----------------
__global__ __launch_bounds__(256) void k_scatter() {
    __shared__ int lcnt[NE], lbase[NE];
    int tid = threadIdx.x;
    if (tid < NE) lcnt[tid] = 0;
    __syncthreads();
    int t = blockIdx.x * 256 + tid;
    int e0 = g_tope[2 * t], e1 = g_tope[2 * t + 1];
    float s0 = g_tops[2 * t], s1 = g_tops[2 * t + 1];
    int p0 = atomicAdd(&lcnt[e0], 1);
    int p1 = atomicAdd(&lcnt[e1], 1);
    __syncthreads();
    if (tid < NE) lbase[tid] = atomicAdd(&g_cur[tid], lcnt[tid]);
    __syncthreads();
    int r0 = g_off[e0] + lbase[e0] + p0;
    int r1 = g_off[e1] + lbase[e1] + p1;
    g_row_tok[r0] = t; g_row_sc[r0] = s0; g_row_slot[r0] = 0;
    g_row_tok[r1] = t; g_row_sc[r1] = s1; g_row_slot[r1] = 1;
}

// ---------------- GEMM kernels ----------------
__global__ __launch_bounds__(256, 1) void tc_gu_routed(const float* __restrict__ x) {
    int e = blockIdx.y >> 5, rt = blockIdx.y & 31;
    int cnt = g_cnt[e];
    int row0 = rt * 128;
    if (row0 >= cnt) return;
    int base = g_off[e];

    extern __shared__ char sm[];
    uint32_t sbu = smem_u32(sm);
    int t = threadIdx.x, rb = t >> 1;
    int rr = base + min(row0 + rb, cnt - 1);
    const float* aptr = x + (size_t)g_row_tok[rr] * HDIM;
    float asc = g_row_sc[rr];
    int n0 = blockIdx.x * 128;
    const __nv_bfloat16* Bh = g_wgu_h + (size_t)e * 2 * IDIM * HDIM + (size_t)n0 * HDIM;
    const __nv_bfloat16* Bl = g_wgu_l + (size_t)e * 2 * IDIM * HDIM + (size_t)n0 * HDIM;

    float acc[2][8][4];
#pragma unroll
    for (int a = 0; a < 2; a++)
#pragma unroll
        for (int b = 0; b < 8; b++)
#pragma unroll
            for (int q = 0; q < 4; q++) acc[a][b][q] = 0.f;

    gemm_core(aptr, asc, Bh, Bl, HDIM, sm, sbu, acc);

    int lane = t & 31, wid = t >> 5, g = lane >> 2, tg = lane & 3;
    int wm0 = (wid >> 1) * 32;
    int jb = n0 / 2 + ((wid & 1) * 64) / 2 + tg;
#pragma unroll
    for (int mi = 0; mi < 2; mi++)
#pragma unroll
        for (int dq = 0; dq < 2; dq++) {
            int rl = wm0 + mi * 16 + g + dq * 8;
            if (row0 + rl < cnt) {
                float* dst = g_act + (size_t)(base + row0 + rl) * IDIM;
#pragma unroll
                for (int nj = 0; nj < 8; nj++)
                    dst[jb + nj * 4] = silu_mul(acc[mi][nj][dq * 2], acc[mi][nj][dq * 2 + 1]);
            }
        }
}

__global__ __launch_bounds__(256, 1) void tc_dn_routed() {
    int e = blockIdx.y >> 5, rt = blockIdx.y & 31;
    int cnt = g_cnt[e];
    int row0 = rt * 128;
    if (row0 >= cnt) return;
    int base = g_off[e];

    extern __shared__ char sm[];
    uint32_t sbu = smem_u32(sm);
    int t = threadIdx.x, rb = t >> 1;
    const float* aptr = g_act + (size_t)(base + min(row0 + rb, cnt - 1)) * IDIM;
    int n0 = blockIdx.x * 128;
    const __nv_bfloat16* Bh = g_wdn_h + (size_t)e * HDIM * IDIM + (size_t)n0 * IDIM;
    const __nv_bfloat16* Bl = g_wdn_l + (size_t)e * HDIM * IDIM + (size_t)n0 * IDIM;

    float acc[2][8][4];
#pragma unroll
    for (int a = 0; a < 2; a++)
#pragma unroll
        for (int b = 0; b < 8; b++)
#pragma unroll
            for (int q = 0; q < 4; q++) acc[a][b][q] = 0.f;

    gemm_core(aptr, 1.f, Bh, Bl, IDIM, sm, sbu, acc);

    int lane = t & 31, wid = t >> 5, g = lane >> 2, tg = lane & 3;
    int wm0 = (wid >> 1) * 32, wn0 = (wid & 1) * 64;
    int colb = n0 + wn0 + tg * 2;
#pragma unroll
    for (int mi = 0; mi < 2; mi++)
#pragma unroll
        for (int dq = 0; dq < 2; dq++) {
            int rl = wm0 + mi * 16 + g + dq * 8;
            if (row0 + rl < cnt) {
                int grow = base + row0 + rl;
                int tok = g_row_tok[grow], slot = g_row_slot[grow];
                float* dst = g_partial[slot] + (size_t)tok * HDIM;
#pragma unroll
                for (int nj = 0; nj < 8; nj++) {
                    float2 v = {acc[mi][nj][dq * 2], acc[mi][nj][dq * 2 + 1]};
                    *(float2*)&dst[colb + nj * 8] = v;
                }
            }
        }
}

__global__ __launch_bounds__(256, 1) void tc_gu_shared(const float* __restrict__ x) {
    int row0 = blockIdx.y * 128;
    int n0 = blockIdx.x * 128;

    extern __shared__ char sm[];
    uint32_t sbu = smem_u32(sm);
    int t = threadIdx.x, rb = t >> 1;
    const float* aptr = x + (size_t)(row0 + rb) * HDIM;
    const __nv_bfloat16* Bh = g_wsg_h + (size_t)n0 * HDIM;
    const __nv_bfloat16* Bl = g_wsg_l + (size_t)n0 * HDIM;

    float acc[2][8][4];
#pragma unroll
    for (int a = 0; a < 2; a++)
#pragma unroll
        for (int b = 0; b < 8; b++)
#pragma unroll
            for (int q = 0; q < 4; q++) acc[a][b][q] = 0.f;

    gemm_core(aptr, 1.f, Bh, Bl, HDIM, sm, sbu, acc);

    int lane = t & 31, wid = t >> 5, g = lane >> 2, tg = lane & 3;
    int wm0 = (wid >> 1) * 32;
    int jb = n0 / 2 + ((wid & 1) * 64) / 2 + tg;
#pragma unroll
    for (int mi = 0; mi < 2; mi++)
#pragma unroll
        for (int dq = 0; dq < 2; dq++) {
            int rl = wm0 + mi * 16 + g + dq * 8;
            float* dst = g_acts + (size_t)(row0 + rl) * IDIM;
#pragma unroll
            for (int nj = 0; nj < 8; nj++)
                dst[jb + nj * 4] = silu_mul(acc[mi][nj][dq * 2], acc[mi][nj][dq * 2 + 1]);
        }
}

__global__ __launch_bounds__(256, 1) void tc_dn_shared(float* __restrict__ out) {
    int row0 = blockIdx.y * 128;
    int n0 = blockIdx.x * 128;

    extern __shared__ char sm[];
    uint32_t sbu = smem_u32(sm);
    int t = threadIdx.x, rb = t >> 1;
    const float* aptr = g_acts + (size_t)(row0 + rb) * IDIM;
    const __nv_bfloat16* Bh = g_wsd_h + (size_t)n0 * IDIM;
    const __nv_bfloat16* Bl = g_wsd_l + (size_t)n0 * IDIM;

    float acc[2][8][4];
#pragma unroll
    for (int a = 0; a < 2; a++)
#pragma unroll
        for (int b = 0; b < 8; b++)
#pragma unroll
            for (int q = 0; q < 4; q++) acc[a][b][q] = 0.f;

    gemm_core(aptr, 1.f, Bh, Bl, IDIM, sm, sbu, acc);

    int lane = t & 31, wid = t >> 5, g = lane >> 2, tg = lane & 3;
    int wm0 = (wid >> 1) * 32, wn0 = (wid & 1) * 64;
    int colb = n0 + wn0 + tg * 2;
#pragma unroll
    for (int mi = 0; mi < 2; mi++)
#pragma unroll
        for (int dq = 0; dq < 2; dq++) {
            int row = row0 + wm0 + mi * 16 + g + dq * 8;
            size_t rbase = (size_t)row * HDIM;
#pragma unroll
            for (int nj = 0; nj < 8; nj++) {
                size_t idx = rbase + colb + nj * 8;
                float2 p0 = *(const float2*)&g_partial[0][idx];
                float2 p1 = *(const float2*)&g_partial[1][idx];
                float2 v;
                v.x = acc[mi][nj][dq * 2] + p0.x + p1.x;
                v.y = acc[mi][nj][dq * 2 + 1] + p0.y + p1.y;
                *(float2*)&out[idx] = v;
            }
        }
}

// ---------------- launch ----------------
extern "C" void kernel_launch(void* const* d_in, const int* in_sizes, int n_in,
                              void* d_out, int out_size) {
    const float* x     = (const float*)d_in[0];   // [T, H]
    const float* rw    = (const float*)d_in[1];   // [E, H]
    const float* gup   = (const float*)d_in[2];   // [E, H, 2I]
    const float* dwn   = (const float*)d_in[3];   // [E, I, H]
    const float* sgate = (const float*)d_in[4];   // [I, H]
    const float* sup   = (const float*)d_in[5];   // [I, H]
    const float* sdown = (const float*)d_in[6];   // [H, I]
    float* out = (float*)d_out;

    float* out_logits = nullptr;
    if (out_size >= TTOK * HDIM + TTOK * NE) out_logits = out + (size_t)TTOK * HDIM;

    cudaFuncSetAttribute(tc_gu_routed, cudaFuncAttributeMaxDynamicSharedMemorySize, SMEM_GEMM);
    cudaFuncSetAttribute(tc_dn_routed, cudaFuncAttributeMaxDynamicSharedMemorySize, SMEM_GEMM);
    cudaFuncSetAttribute(tc_gu_shared, cudaFuncAttributeMaxDynamicSharedMemorySize, SMEM_GEMM);
    cudaFuncSetAttribute(tc_dn_shared, cudaFuncAttributeMaxDynamicSharedMemorySize, SMEM_GEMM);

    k_init<<<1, 32>>>();
    k_router<<<TTOK / 4, 128>>>(x, rw, out_logits);
    k_prefix<<<1, 32>>>();
    k_scatter<<<TTOK / 256, 256>>>();

    // weight conversions (bf16 hi/lo, mma-friendly layouts)
    k_cvt_gup<<<dim3(2 * IDIM / 32, HDIM / 32, NE), dim3(32, 8)>>>(gup);
    k_cvt_dwn<<<dim3(HDIM / 32, IDIM / 32, NE), dim3(32, 8)>>>(dwn);
    k_cvt_sharedgu<<<(IDIM * HDIM) / 256, 256>>>(sgate, sup);
    k_cvt_shareddn<<<(HDIM * IDIM) / 256, 256>>>(sdown);

    tc_gu_routed<<<dim3(2 * IDIM / 128, NE * 32), 256, SMEM_GEMM>>>(x);
    tc_dn_routed<<<dim3(HDIM / 128, NE * 32), 256, SMEM_GEMM>>>();
    tc_gu_shared<<<dim3(2 * IDIM / 128, TTOK / 128), 256, SMEM_GEMM>>>(x);
    tc_dn_shared<<<dim3(HDIM / 128, TTOK / 128), 256, SMEM_GEMM>>>(out);
}

// round 6
// speedup vs baseline: 2.2584x; 1.2968x over previous
#include <cuda_runtime.h>
#include <cuda_fp16.h>
#include <stdint.h>
#include <math.h>

// Problem constants
#define TTOK 4096
#define HDIM 1024
#define IDIM 2048
#define NE   8
#define NPAIR (TTOK * 2)

// GEMM config: 128x128 CTA tile, 8 warps (4M x 2N), KC=32, double-buffered
#define KC 32
#define A_PITCH 80               // bytes per smem row (40 fp16, conflict-free frag loads)
#define SM_AH 0
#define SM_AL 10240
#define SM_BH 20480
#define SM_STAGE 30720
#define SMEM_GEMM (2 * SM_STAGE) // 61440 B

// ---------------- scratch (static __device__ — no allocation) ----------------
__device__ float g_act[(size_t)NPAIR * IDIM];          // routed swiglu activations
__device__ float g_acts[(size_t)TTOK * IDIM];          // shared swiglu activations
__device__ float g_partial[2][(size_t)TTOK * HDIM];    // per-slot routed outputs
__device__ int   g_row_tok[NPAIR];
__device__ float g_row_sc[NPAIR];
__device__ int   g_row_slot[NPAIR];
__device__ int   g_tope[NPAIR];
__device__ float g_tops[NPAIR];
__device__ int   g_cnt[NE];
__device__ int   g_off[NE];
__device__ int   g_cur[NE];

// fp16 weights, [n][k] col-major-for-mma layouts (single precision-rounded copy)
__device__ __half g_wgu[(size_t)NE * 2 * IDIM * HDIM];   // interleaved gate/up rows
__device__ __half g_wdn[(size_t)NE * HDIM * IDIM];       // [H][I]
__device__ __half g_wsg[(size_t)2 * IDIM * HDIM];        // shared gate/up interleaved
__device__ __half g_wsd[(size_t)HDIM * IDIM];            // [H][I]

// ---------------- small helpers ----------------
__device__ __forceinline__ uint32_t smem_u32(const void* p) {
    uint32_t a;
    asm("{ .reg .u64 t; cvta.to.shared.u64 t, %1; cvt.u32.u64 %0, t; }" : "=r"(a) : "l"(p));
    return a;
}
__device__ __forceinline__ void cpa16(uint32_t saddr, const void* g) {
    asm volatile("cp.async.ca.shared.global [%0], [%1], 16;" :: "r"(saddr), "l"(g));
}
__device__ __forceinline__ void cpa_commit() {
    asm volatile("cp.async.commit_group;" ::: "memory");
}
__device__ __forceinline__ void cpa_wait0() {
    asm volatile("cp.async.wait_group 0;" ::: "memory");
}
__device__ __forceinline__ uint32_t packraw(__half a, __half b) {
    __half2 t(a, b);
    return *reinterpret_cast<uint32_t*>(&t);
}
__device__ __forceinline__ uint32_t packh2(float a, float b) {
    __half2 t = __floats2half2_rn(a, b);
    return *reinterpret_cast<uint32_t*>(&t);
}
__device__ __forceinline__ float silu_mul(float g, float u) {
    return u * g / (1.f + __expf(-g));
}
__device__ __forceinline__ void mma16816(float d[4], uint32_t a0, uint32_t a1, uint32_t a2,
                                         uint32_t a3, uint32_t b0, uint32_t b1) {
    asm volatile(
        "mma.sync.aligned.m16n8k16.row.col.f32.f16.f16.f32 "
        "{%0,%1,%2,%3}, {%4,%5,%6,%7}, {%8,%9}, {%0,%1,%2,%3};"
        : "+f"(d[0]), "+f"(d[1]), "+f"(d[2]), "+f"(d[3])
        : "r"(a0), "r"(a1), "r"(a2), "r"(a3), "r"(b0), "r"(b1));
}

// ---------------- GEMM core: C[128x128] += A(fp32, hi/lo split) * B(fp16, [n][k]) ----------------
__device__ __forceinline__ void gemm_core(const float* __restrict__ aptr, float asc,
                                          const __half* __restrict__ Bh,
                                          int Ktot, char* sm, uint32_t sbu,
                                          float acc[2][8][4]) {
    const int t = threadIdx.x;
    const int lane = t & 31, wid = t >> 5;
    const int g = lane >> 2, tg = lane & 3;
    const int wm0 = (wid >> 1) * 32, wn0 = (wid & 1) * 64;
    const int rb = t >> 1, half = t & 1;
    const int nc = Ktot / KC;

    const float* ap = aptr + half * 16;
    const __half* bhp = Bh + (size_t)rb * Ktot + half * 16;
    const uint32_t sBh = sbu + SM_BH + rb * A_PITCH + half * 32;

    float av[16];

    // prologue: chunk 0
    {
        const float4* p = (const float4*)ap;
#pragma unroll
        for (int i = 0; i < 4; i++) {
            float4 v = p[i];
            av[i * 4 + 0] = v.x; av[i * 4 + 1] = v.y;
            av[i * 4 + 2] = v.z; av[i * 4 + 3] = v.w;
        }
        cpa16(sBh, bhp); cpa16(sBh + 16, bhp + 8);
        cpa_commit();
        char* dh = sm + SM_AH + rb * A_PITCH + half * 32;
        char* dl = sm + SM_AL + rb * A_PITCH + half * 32;
#pragma unroll
        for (int i = 0; i < 8; i++) {
            float x0 = av[2 * i] * asc, x1 = av[2 * i + 1] * asc;
            __half h0 = __float2half_rn(x0), h1 = __float2half_rn(x1);
            *(uint32_t*)(dh + i * 4) = packraw(h0, h1);
            *(uint32_t*)(dl + i * 4) =
                packh2(x0 - __half2float(h0), x1 - __half2float(h1));
        }
    }

    for (int c = 0; c < nc; c++) {
        const int s = c & 1;
        cpa_wait0();
        __syncthreads();
        const bool more = (c + 1 < nc);
        if (more) {
            const float4* p = (const float4*)(ap + (c + 1) * KC);
#pragma unroll
            for (int i = 0; i < 4; i++) {
                float4 v = p[i];
                av[i * 4 + 0] = v.x; av[i * 4 + 1] = v.y;
                av[i * 4 + 2] = v.z; av[i * 4 + 3] = v.w;
            }
            const uint32_t so = (1 - s) * SM_STAGE;
            const __half* ph = bhp + (c + 1) * KC;
            cpa16(sBh + so, ph); cpa16(sBh + so + 16, ph + 8);
            cpa_commit();
        }
        // MMA on stage s
        {
            const char* sA_h = sm + s * SM_STAGE + SM_AH;
            const char* sA_l = sm + s * SM_STAGE + SM_AL;
            const char* sB_h = sm + s * SM_STAGE + SM_BH;
#pragma unroll
            for (int ks = 0; ks < 2; ks++) {
                uint32_t ah[2][4], al[2][4];
#pragma unroll
                for (int mi = 0; mi < 2; mi++) {
                    int rbase = (wm0 + mi * 16 + g) * A_PITCH + ks * 32 + tg * 4;
                    ah[mi][0] = *(const uint32_t*)(sA_h + rbase);
                    ah[mi][1] = *(const uint32_t*)(sA_h + rbase + 8 * A_PITCH);
                    ah[mi][2] = *(const uint32_t*)(sA_h + rbase + 16);
                    ah[mi][3] = *(const uint32_t*)(sA_h + rbase + 8 * A_PITCH + 16);
                    al[mi][0] = *(const uint32_t*)(sA_l + rbase);
                    al[mi][1] = *(const uint32_t*)(sA_l + rbase + 8 * A_PITCH);
                    al[mi][2] = *(const uint32_t*)(sA_l + rbase + 16);
                    al[mi][3] = *(const uint32_t*)(sA_l + rbase + 8 * A_PITCH + 16);
                }
#pragma unroll
                for (int nj = 0; nj < 8; nj++) {
                    int nb = (wn0 + nj * 8 + g) * A_PITCH + ks * 32 + tg * 4;
                    uint32_t bh0 = *(const uint32_t*)(sB_h + nb);
                    uint32_t bh1 = *(const uint32_t*)(sB_h + nb + 16);
#pragma unroll
                    for (int mi = 0; mi < 2; mi++) {
                        mma16816(acc[mi][nj], ah[mi][0], ah[mi][1], ah[mi][2], ah[mi][3], bh0, bh1);
                        mma16816(acc[mi][nj], al[mi][0], al[mi][1], al[mi][2], al[mi][3], bh0, bh1);
                    }
                }
            }
        }
        if (more) {
            char* dh = sm + (1 - s) * SM_STAGE + SM_AH + rb * A_PITCH + half * 32;
            char* dl = sm + (1 - s) * SM_STAGE + SM_AL + rb * A_PITCH + half * 32;
#pragma unroll
            for (int i = 0; i < 8; i++) {
                float x0 = av[2 * i] * asc, x1 = av[2 * i + 1] * asc;
                __half h0 = __float2half_rn(x0), h1 = __float2half_rn(x1);
                *(uint32_t*)(dh + i * 4) = packraw(h0, h1);
                *(uint32_t*)(dl + i * 4) =
                    packh2(x0 - __half2float(h0), x1 - __half2float(h1));
            }
        }
    }
}

// ---------------- weight conversion ----------------
// transpose-convert: src fp32 [K][N] (per-expert) -> dst fp16 [n'][K]
__device__ __forceinline__ void cvt_T_body(const float* __restrict__ s,
                                           __half* __restrict__ oh,
                                           int K, int N, int remap_half) {
    __shared__ float tile[32][33];
    int c0 = blockIdx.x * 32;
    int k0 = blockIdx.y * 32;
    int tx = threadIdx.x, ty = threadIdx.y;
#pragma unroll
    for (int i = 0; i < 4; i++) {
        int k = ty + i * 8;
        tile[k][tx] = s[(size_t)(k0 + k) * N + c0 + tx];
    }
    __syncthreads();
#pragma unroll
    for (int i = 0; i < 4; i++) {
        int cc = c0 + ty + i * 8;
        int n = remap_half ? (2 * (cc % remap_half) + cc / remap_half) : cc;
        oh[(size_t)n * K + k0 + tx] = __float2half_rn(tile[tx][ty + i * 8]);
    }
}

__global__ void k_cvt_gup(const float* __restrict__ gup) {
    int e = blockIdx.z;
    cvt_T_body(gup + (size_t)e * HDIM * 2 * IDIM,
               g_wgu + (size_t)e * 2 * IDIM * HDIM, HDIM, 2 * IDIM, IDIM);
}
__global__ void k_cvt_dwn(const float* __restrict__ dwn) {
    int e = blockIdx.z;
    cvt_T_body(dwn + (size_t)e * IDIM * HDIM,
               g_wdn + (size_t)e * HDIM * IDIM, IDIM, HDIM, 0);
}
__global__ void k_cvt_sharedgu(const float* __restrict__ gw, const float* __restrict__ uw) {
    size_t id = (size_t)blockIdx.x * 256 + threadIdx.x;   // over I*H
    int j = (int)(id / HDIM), k = (int)(id % HDIM);
    g_wsg[(size_t)(2 * j) * HDIM + k]     = __float2half_rn(gw[id]);
    g_wsg[(size_t)(2 * j + 1) * HDIM + k] = __float2half_rn(uw[id]);
}
__global__ void k_cvt_shareddn(const float* __restrict__ dw) {
    size_t id = (size_t)blockIdx.x * 256 + threadIdx.x;   // over H*I
    g_wsd[id] = __float2half_rn(dw[id]);
}

// ---------------- tiny control kernels ----------------
__global__ void k_init() { if (threadIdx.x < NE) g_cnt[threadIdx.x] = 0; }
__global__ void k_prefix() {
    if (threadIdx.x == 0) {
        int s = 0;
        for (int e = 0; e < NE; e++) { g_off[e] = s; s += g_cnt[e]; }
    }
    if (threadIdx.x < NE) g_cur[threadIdx.x] = 0;
}

// ---------------- router ----------------
__global__ __launch_bounds__(128) void k_router(const float* __restrict__ x,
                                                const float* __restrict__ rw,
                                                float* __restrict__ out_logits) {
    int warp = threadIdx.x >> 5, lane = threadIdx.x & 31;
    int t = blockIdx.x * 4 + warp;
    if (t >= TTOK) return;
    const float* xr = x + (size_t)t * HDIM;
    float acc[NE];
#pragma unroll
    for (int e = 0; e < NE; e++) acc[e] = 0.f;
    for (int i = lane; i < HDIM; i += 32) {
        float xv = xr[i];
#pragma unroll
        for (int e = 0; e < NE; e++) acc[e] = fmaf(xv, rw[e * HDIM + i], acc[e]);
    }
#pragma unroll
    for (int e = 0; e < NE; e++) {
#pragma unroll
        for (int o = 16; o > 0; o >>= 1) acc[e] += __shfl_xor_sync(0xFFFFFFFFu, acc[e], o);
    }
    if (lane == 0) {
        if (out_logits) {
#pragma unroll
            for (int e = 0; e < NE; e++) out_logits[(size_t)t * NE + e] = acc[e];
        }
        int e1 = 0; float v1 = acc[0];
#pragma unroll
        for (int e = 1; e < NE; e++) if (acc[e] > v1) { v1 = acc[e]; e1 = e; }
        int e2 = -1; float v2 = -1e30f;
#pragma unroll
        for (int e = 0; e < NE; e++) if (e != e1 && acc[e] > v2) { v2 = acc[e]; e2 = e; }
        float s1 = 1.f / (1.f + __expf(-v1));
        float s2 = 1.f / (1.f + __expf(-v2));
        g_tope[t * 2 + 0] = e1; g_tops[t * 2 + 0] = s1;
        g_tope[t * 2 + 1] = e2; g_tops[t * 2 + 1] = s2;
        atomicAdd(&g_cnt[e1], 1);
        atomicAdd(&g_cnt[e2], 1);
    }
}

// ---------------- scatter ----------------
__global__ __launch_bounds__(256) void k_scatter() {
    __shared__ int lcnt[NE], lbase[NE];
    int tid = threadIdx.x;
    if (tid < NE) lcnt[tid] = 0;
    __syncthreads();
    int t = blockIdx.x * 256 + tid;
    int e0 = g_tope[2 * t], e1 = g_tope[2 * t + 1];
    float s0 = g_tops[2 * t], s1 = g_tops[2 * t + 1];
    int p0 = atomicAdd(&lcnt[e0], 1);
    int p1 = atomicAdd(&lcnt[e1], 1);
    __syncthreads();
    if (tid < NE) lbase[tid] = atomicAdd(&g_cur[tid], lcnt[tid]);
    __syncthreads();
    int r0 = g_off[e0] + lbase[e0] + p0;
    int r1 = g_off[e1] + lbase[e1] + p1;
    g_row_tok[r0] = t; g_row_sc[r0] = s0; g_row_slot[r0] = 0;
    g_row_tok[r1] = t; g_row_sc[r1] = s1; g_row_slot[r1] = 1;
}

// ---------------- GEMM kernels ----------------
__global__ __launch_bounds__(256, 1) void tc_gu_routed(const float* __restrict__ x) {
    int e = blockIdx.y >> 5, rt = blockIdx.y & 31;
    int cnt = g_cnt[e];
    int row0 = rt * 128;
    if (row0 >= cnt) return;
    int base = g_off[e];

    extern __shared__ char sm[];
    uint32_t sbu = smem_u32(sm);
    int t = threadIdx.x, rb = t >> 1;
    int rr = base + min(row0 + rb, cnt - 1);
    const float* aptr = x + (size_t)g_row_tok[rr] * HDIM;
    float asc = g_row_sc[rr];
    int n0 = blockIdx.x * 128;
    const __half* Bh = g_wgu + (size_t)e * 2 * IDIM * HDIM + (size_t)n0 * HDIM;

    float acc[2][8][4];
#pragma unroll
    for (int a = 0; a < 2; a++)
#pragma unroll
        for (int b = 0; b < 8; b++)
#pragma unroll
            for (int q = 0; q < 4; q++) acc[a][b][q] = 0.f;

    gemm_core(aptr, asc, Bh, HDIM, sm, sbu, acc);

    int lane = t & 31, wid = t >> 5, g = lane >> 2, tg = lane & 3;
    int wm0 = (wid >> 1) * 32;
    int jb = n0 / 2 + ((wid & 1) * 64) / 2 + tg;
#pragma unroll
    for (int mi = 0; mi < 2; mi++)
#pragma unroll
        for (int dq = 0; dq < 2; dq++) {
            int rl = wm0 + mi * 16 + g + dq * 8;
            if (row0 + rl < cnt) {
                float* dst = g_act + (size_t)(base + row0 + rl) * IDIM;
#pragma unroll
                for (int nj = 0; nj < 8; nj++)
                    dst[jb + nj * 4] = silu_mul(acc[mi][nj][dq * 2], acc[mi][nj][dq * 2 + 1]);
            }
        }
}

__global__ __launch_bounds__(256, 1) void tc_dn_routed() {
    int e = blockIdx.y >> 5, rt = blockIdx.y & 31;
    int cnt = g_cnt[e];
    int row0 = rt * 128;
    if (row0 >= cnt) return;
    int base = g_off[e];

    extern __shared__ char sm[];
    uint32_t sbu = smem_u32(sm);
    int t = threadIdx.x, rb = t >> 1;
    const float* aptr = g_act + (size_t)(base + min(row0 + rb, cnt - 1)) * IDIM;
    int n0 = blockIdx.x * 128;
    const __half* Bh = g_wdn + (size_t)e * HDIM * IDIM + (size_t)n0 * IDIM;

    float acc[2][8][4];
#pragma unroll
    for (int a = 0; a < 2; a++)
#pragma unroll
        for (int b = 0; b < 8; b++)
#pragma unroll
            for (int q = 0; q < 4; q++) acc[a][b][q] = 0.f;

    gemm_core(aptr, 1.f, Bh, IDIM, sm, sbu, acc);

    int lane = t & 31, wid = t >> 5, g = lane >> 2, tg = lane & 3;
    int wm0 = (wid >> 1) * 32, wn0 = (wid & 1) * 64;
    int colb = n0 + wn0 + tg * 2;
#pragma unroll
    for (int mi = 0; mi < 2; mi++)
#pragma unroll
        for (int dq = 0; dq < 2; dq++) {
            int rl = wm0 + mi * 16 + g + dq * 8;
            if (row0 + rl < cnt) {
                int grow = base + row0 + rl;
                int tok = g_row_tok[grow], slot = g_row_slot[grow];
                float* dst = g_partial[slot] + (size_t)tok * HDIM;
#pragma unroll
                for (int nj = 0; nj < 8; nj++) {
                    float2 v = {acc[mi][nj][dq * 2], acc[mi][nj][dq * 2 + 1]};
                    *(float2*)&dst[colb + nj * 8] = v;
                }
            }
        }
}

__global__ __launch_bounds__(256, 1) void tc_gu_shared(const float* __restrict__ x) {
    int row0 = blockIdx.y * 128;
    int n0 = blockIdx.x * 128;

    extern __shared__ char sm[];
    uint32_t sbu = smem_u32(sm);
    int t = threadIdx.x, rb = t >> 1;
    const float* aptr = x + (size_t)(row0 + rb) * HDIM;
    const __half* Bh = g_wsg + (size_t)n0 * HDIM;

    float acc[2][8][4];
#pragma unroll
    for (int a = 0; a < 2; a++)
#pragma unroll
        for (int b = 0; b < 8; b++)
#pragma unroll
            for (int q = 0; q < 4; q++) acc[a][b][q] = 0.f;

    gemm_core(aptr, 1.f, Bh, HDIM, sm, sbu, acc);

    int lane = t & 31, wid = t >> 5, g = lane >> 2, tg = lane & 3;
    int wm0 = (wid >> 1) * 32;
    int jb = n0 / 2 + ((wid & 1) * 64) / 2 + tg;
#pragma unroll
    for (int mi = 0; mi < 2; mi++)
#pragma unroll
        for (int dq = 0; dq < 2; dq++) {
            int rl = wm0 + mi * 16 + g + dq * 8;
            float* dst = g_acts + (size_t)(row0 + rl) * IDIM;
#pragma unroll
            for (int nj = 0; nj < 8; nj++)
                dst[jb + nj * 4] = silu_mul(acc[mi][nj][dq * 2], acc[mi][nj][dq * 2 + 1]);
        }
}

__global__ __launch_bounds__(256, 1) void tc_dn_shared(float* __restrict__ out) {
    int row0 = blockIdx.y * 128;
    int n0 = blockIdx.x * 128;

    extern __shared__ char sm[];
    uint32_t sbu = smem_u32(sm);
    int t = threadIdx.x, rb = t >> 1;
    const float* aptr = g_acts + (size_t)(row0 + rb) * IDIM;
    const __half* Bh = g_wsd + (size_t)n0 * IDIM;

    float acc[2][8][4];
#pragma unroll
    for (int a = 0; a < 2; a++)
#pragma unroll
        for (int b = 0; b < 8; b++)
#pragma unroll
            for (int q = 0; q < 4; q++) acc[a][b][q] = 0.f;

    gemm_core(aptr, 1.f, Bh, IDIM, sm, sbu, acc);

    int lane = t & 31, wid = t >> 5, g = lane >> 2, tg = lane & 3;
    int wm0 = (wid >> 1) * 32, wn0 = (wid & 1) * 64;
    int colb = n0 + wn0 + tg * 2;
#pragma unroll
    for (int mi = 0; mi < 2; mi++)
#pragma unroll
        for (int dq = 0; dq < 2; dq++) {
            int row = row0 + wm0 + mi * 16 + g + dq * 8;
            size_t rbase = (size_t)row * HDIM;
#pragma unroll
            for (int nj = 0; nj < 8; nj++) {
                size_t idx = rbase + colb + nj * 8;
                float2 p0 = *(const float2*)&g_partial[0][idx];
                float2 p1 = *(const float2*)&g_partial[1][idx];
                float2 v;
                v.x = acc[mi][nj][dq * 2] + p0.x + p1.x;
                v.y = acc[mi][nj][dq * 2 + 1] + p0.y + p1.y;
                *(float2*)&out[idx] = v;
            }
        }
}

// ---------------- launch ----------------
extern "C" void kernel_launch(void* const* d_in, const int* in_sizes, int n_in,
                              void* d_out, int out_size) {
    const float* x     = (const float*)d_in[0];   // [T, H]
    const float* rw    = (const float*)d_in[1];   // [E, H]
    const float* gup   = (const float*)d_in[2];   // [E, H, 2I]
    const float* dwn   = (const float*)d_in[3];   // [E, I, H]
    const float* sgate = (const float*)d_in[4];   // [I, H]
    const float* sup   = (const float*)d_in[5];   // [I, H]
    const float* sdown = (const float*)d_in[6];   // [H, I]
    float* out = (float*)d_out;

    float* out_logits = nullptr;
    if (out_size >= TTOK * HDIM + TTOK * NE) out_logits = out + (size_t)TTOK * HDIM;

    cudaFuncSetAttribute(tc_gu_routed, cudaFuncAttributeMaxDynamicSharedMemorySize, SMEM_GEMM);
    cudaFuncSetAttribute(tc_dn_routed, cudaFuncAttributeMaxDynamicSharedMemorySize, SMEM_GEMM);
    cudaFuncSetAttribute(tc_gu_shared, cudaFuncAttributeMaxDynamicSharedMemorySize, SMEM_GEMM);
    cudaFuncSetAttribute(tc_dn_shared, cudaFuncAttributeMaxDynamicSharedMemorySize, SMEM_GEMM);

    k_init<<<1, 32>>>();
    k_router<<<TTOK / 4, 128>>>(x, rw, out_logits);
    k_prefix<<<1, 32>>>();
    k_scatter<<<TTOK / 256, 256>>>();

    // weight conversions (fp16, mma-friendly layouts)
    k_cvt_gup<<<dim3(2 * IDIM / 32, HDIM / 32, NE), dim3(32, 8)>>>(gup);
    k_cvt_dwn<<<dim3(HDIM / 32, IDIM / 32, NE), dim3(32, 8)>>>(dwn);
    k_cvt_sharedgu<<<(IDIM * HDIM) / 256, 256>>>(sgate, sup);
    k_cvt_shareddn<<<(HDIM * IDIM) / 256, 256>>>(sdown);

    tc_gu_routed<<<dim3(2 * IDIM / 128, NE * 32), 256, SMEM_GEMM>>>(x);
    tc_dn_routed<<<dim3(HDIM / 128, NE * 32), 256, SMEM_GEMM>>>();
    tc_gu_shared<<<dim3(2 * IDIM / 128, TTOK / 128), 256, SMEM_GEMM>>>(x);
    tc_dn_shared<<<dim3(HDIM / 128, TTOK / 128), 256, SMEM_GEMM>>>(out);
}

// round 7
// speedup vs baseline: 2.7457x; 1.2158x over previous
#include <cuda_runtime.h>
#include <cuda_fp16.h>
#include <stdint.h>
#include <math.h>

// Problem constants
#define TTOK 4096
#define HDIM 1024
#define IDIM 2048
#define NE   8
#define NPAIR (TTOK * 2)

// GEMM config: 128x128 CTA tile, 8 warps (4M x 2N), KC=32, double-buffered
#define KC 32
#define A_PITCH 80               // bytes per smem row (40 fp16, conflict-free frag loads)
#define SM_AH 0
#define SM_AL 10240
#define SM_BH 20480
#define SM_STAGE 30720
#define SMEM_GEMM (2 * SM_STAGE) // 61440 B -> 2 CTAs/SM

// ---------------- scratch (static __device__ — no allocation) ----------------
__device__ __half g_x_h[(size_t)TTOK * HDIM];           // x hi
__device__ __half g_x_l[(size_t)TTOK * HDIM];           // x lo
__device__ __half g_act_h[(size_t)NPAIR * IDIM];        // routed swiglu act hi
__device__ __half g_act_l[(size_t)NPAIR * IDIM];        // routed swiglu act lo
__device__ __half g_acts_h[(size_t)TTOK * IDIM];        // shared swiglu act hi
__device__ __half g_acts_l[(size_t)TTOK * IDIM];        // shared swiglu act lo
__device__ float g_partial[2][(size_t)TTOK * HDIM];     // per-slot routed outputs
__device__ int   g_row_tok[NPAIR];
__device__ float g_row_sc[NPAIR];
__device__ int   g_row_slot[NPAIR];
__device__ int   g_tope[NPAIR];
__device__ float g_tops[NPAIR];
__device__ int   g_cnt[NE];
__device__ int   g_off[NE];
__device__ int   g_cur[NE];

// fp16 weights, [n][k] col-major-for-mma layouts
__device__ __half g_wgu[(size_t)NE * 2 * IDIM * HDIM];   // interleaved gate/up rows
__device__ __half g_wdn[(size_t)NE * HDIM * IDIM];       // [H][I]
__device__ __half g_wsg[(size_t)2 * IDIM * HDIM];        // shared gate/up interleaved
__device__ __half g_wsd[(size_t)HDIM * IDIM];            // [H][I]

// ---------------- small helpers ----------------
__device__ __forceinline__ uint32_t smem_u32(const void* p) {
    uint32_t a;
    asm("{ .reg .u64 t; cvta.to.shared.u64 t, %1; cvt.u32.u64 %0, t; }" : "=r"(a) : "l"(p));
    return a;
}
__device__ __forceinline__ void cpa16(uint32_t saddr, const void* g) {
    asm volatile("cp.async.ca.shared.global [%0], [%1], 16;" :: "r"(saddr), "l"(g));
}
__device__ __forceinline__ void cpa_commit() {
    asm volatile("cp.async.commit_group;" ::: "memory");
}
__device__ __forceinline__ void cpa_wait0() {
    asm volatile("cp.async.wait_group 0;" ::: "memory");
}
__device__ __forceinline__ float silu_mul(float g, float u) {
    return u * g / (1.f + __expf(-g));
}
__device__ __forceinline__ void mma16816(float d[4], uint32_t a0, uint32_t a1, uint32_t a2,
                                         uint32_t a3, uint32_t b0, uint32_t b1) {
    asm volatile(
        "mma.sync.aligned.m16n8k16.row.col.f32.f16.f16.f32 "
        "{%0,%1,%2,%3}, {%4,%5,%6,%7}, {%8,%9}, {%0,%1,%2,%3};"
        : "+f"(d[0]), "+f"(d[1]), "+f"(d[2]), "+f"(d[3])
        : "r"(a0), "r"(a1), "r"(a2), "r"(a3), "r"(b0), "r"(b1));
}

// ---------------- GEMM core: C[128x128] += (Ah+Al) * B  (all fp16 in gmem) ----------------
// ah_p/al_p/b_p: per-thread source pointers, already offset to (row rb, half*16).
__device__ __forceinline__ void gemm_core(const __half* __restrict__ ah_p,
                                          const __half* __restrict__ al_p,
                                          const __half* __restrict__ b_p,
                                          int Ktot, char* sm, uint32_t sbu,
                                          float acc[2][8][4]) {
    const int t = threadIdx.x;
    const int lane = t & 31, wid = t >> 5;
    const int g = lane >> 2, tg = lane & 3;
    const int wm0 = (wid >> 1) * 32, wn0 = (wid & 1) * 64;
    const int rb = t >> 1, half = t & 1;
    const int nc = Ktot / KC;

    const uint32_t sA_h = sbu + SM_AH + rb * A_PITCH + half * 32;
    const uint32_t sA_l = sbu + SM_AL + rb * A_PITCH + half * 32;
    const uint32_t sB   = sbu + SM_BH + rb * A_PITCH + half * 32;

    // prologue: chunk 0 into stage 0
    cpa16(sA_h, ah_p); cpa16(sA_h + 16, ah_p + 8);
    cpa16(sA_l, al_p); cpa16(sA_l + 16, al_p + 8);
    cpa16(sB,   b_p);  cpa16(sB + 16,   b_p + 8);
    cpa_commit();

    for (int c = 0; c < nc; c++) {
        const int s = c & 1;
        cpa_wait0();
        __syncthreads();
        if (c + 1 < nc) {
            const uint32_t so = (1 - s) * SM_STAGE;
            const __half* ph = ah_p + (c + 1) * KC;
            const __half* pl = al_p + (c + 1) * KC;
            const __half* pb = b_p  + (c + 1) * KC;
            cpa16(sA_h + so, ph); cpa16(sA_h + so + 16, ph + 8);
            cpa16(sA_l + so, pl); cpa16(sA_l + so + 16, pl + 8);
            cpa16(sB + so,   pb); cpa16(sB + so + 16,   pb + 8);
            cpa_commit();
        }
        const char* pAh = sm + s * SM_STAGE + SM_AH;
        const char* pAl = sm + s * SM_STAGE + SM_AL;
        const char* pB  = sm + s * SM_STAGE + SM_BH;
#pragma unroll
        for (int ks = 0; ks < 2; ks++) {
            uint32_t ah[2][4], al[2][4];
#pragma unroll
            for (int mi = 0; mi < 2; mi++) {
                int rbase = (wm0 + mi * 16 + g) * A_PITCH + ks * 32 + tg * 4;
                ah[mi][0] = *(const uint32_t*)(pAh + rbase);
                ah[mi][1] = *(const uint32_t*)(pAh + rbase + 8 * A_PITCH);
                ah[mi][2] = *(const uint32_t*)(pAh + rbase + 16);
                ah[mi][3] = *(const uint32_t*)(pAh + rbase + 8 * A_PITCH + 16);
                al[mi][0] = *(const uint32_t*)(pAl + rbase);
                al[mi][1] = *(const uint32_t*)(pAl + rbase + 8 * A_PITCH);
                al[mi][2] = *(const uint32_t*)(pAl + rbase + 16);
                al[mi][3] = *(const uint32_t*)(pAl + rbase + 8 * A_PITCH + 16);
            }
#pragma unroll
            for (int nj = 0; nj < 8; nj++) {
                int nb = (wn0 + nj * 8 + g) * A_PITCH + ks * 32 + tg * 4;
                uint32_t b0 = *(const uint32_t*)(pB + nb);
                uint32_t b1 = *(const uint32_t*)(pB + nb + 16);
#pragma unroll
                for (int mi = 0; mi < 2; mi++) {
                    mma16816(acc[mi][nj], ah[mi][0], ah[mi][1], ah[mi][2], ah[mi][3], b0, b1);
                    mma16816(acc[mi][nj], al[mi][0], al[mi][1], al[mi][2], al[mi][3], b0, b1);
                }
            }
        }
    }
}

// ---------------- conversions ----------------
__global__ void k_cvt_x(const float* __restrict__ x) {
    size_t id = (size_t)blockIdx.x * 256 + threadIdx.x;
    float v = x[id];
    __half h = __float2half_rn(v);
    g_x_h[id] = h;
    g_x_l[id] = __float2half_rn(v - __half2float(h));
}

// transpose-convert: src fp32 [K][N] (per-expert) -> dst fp16 [n'][K]
__device__ __forceinline__ void cvt_T_body(const float* __restrict__ s,
                                           __half* __restrict__ oh,
                                           int K, int N, int remap_half) {
    __shared__ float tile[32][33];
    int c0 = blockIdx.x * 32;
    int k0 = blockIdx.y * 32;
    int tx = threadIdx.x, ty = threadIdx.y;
#pragma unroll
    for (int i = 0; i < 4; i++) {
        int k = ty + i * 8;
        tile[k][tx] = s[(size_t)(k0 + k) * N + c0 + tx];
    }
    __syncthreads();
#pragma unroll
    for (int i = 0; i < 4; i++) {
        int cc = c0 + ty + i * 8;
        int n = remap_half ? (2 * (cc % remap_half) + cc / remap_half) : cc;
        oh[(size_t)n * K + k0 + tx] = __float2half_rn(tile[tx][ty + i * 8]);
    }
}

__global__ void k_cvt_gup(const float* __restrict__ gup) {
    int e = blockIdx.z;
    cvt_T_body(gup + (size_t)e * HDIM * 2 * IDIM,
               g_wgu + (size_t)e * 2 * IDIM * HDIM, HDIM, 2 * IDIM, IDIM);
}
__global__ void k_cvt_dwn(const float* __restrict__ dwn) {
    int e = blockIdx.z;
    cvt_T_body(dwn + (size_t)e * IDIM * HDIM,
               g_wdn + (size_t)e * HDIM * IDIM, IDIM, HDIM, 0);
}
__global__ void k_cvt_sharedgu(const float* __restrict__ gw, const float* __restrict__ uw) {
    size_t id = (size_t)blockIdx.x * 256 + threadIdx.x;   // over I*H
    int j = (int)(id / HDIM), k = (int)(id % HDIM);
    g_wsg[(size_t)(2 * j) * HDIM + k]     = __float2half_rn(gw[id]);
    g_wsg[(size_t)(2 * j + 1) * HDIM + k] = __float2half_rn(uw[id]);
}
__global__ void k_cvt_shareddn(const float* __restrict__ dw) {
    size_t id = (size_t)blockIdx.x * 256 + threadIdx.x;   // over H*I
    g_wsd[id] = __float2half_rn(dw[id]);
}

// ---------------- tiny control kernels ----------------
__global__ void k_init() { if (threadIdx.x < NE) g_cnt[threadIdx.x] = 0; }
__global__ void k_prefix() {
    if (threadIdx.x == 0) {
        int s = 0;
        for (int e = 0; e < NE; e++) { g_off[e] = s; s += g_cnt[e]; }
    }
    if (threadIdx.x < NE) g_cur[threadIdx.x] = 0;
}

// ---------------- router ----------------
__global__ __launch_bounds__(128) void k_router(const float* __restrict__ x,
                                                const float* __restrict__ rw,
                                                float* __restrict__ out_logits) {
    int warp = threadIdx.x >> 5, lane = threadIdx.x & 31;
    int t = blockIdx.x * 4 + warp;
    if (t >= TTOK) return;
    const float* xr = x + (size_t)t * HDIM;
    float acc[NE];
#pragma unroll
    for (int e = 0; e < NE; e++) acc[e] = 0.f;
    for (int i = lane; i < HDIM; i += 32) {
        float xv = xr[i];
#pragma unroll
        for (int e = 0; e < NE; e++) acc[e] = fmaf(xv, rw[e * HDIM + i], acc[e]);
    }
#pragma unroll
    for (int e = 0; e < NE; e++) {
#pragma unroll
        for (int o = 16; o > 0; o >>= 1) acc[e] += __shfl_xor_sync(0xFFFFFFFFu, acc[e], o);
    }
    if (lane == 0) {
        if (out_logits) {
#pragma unroll
            for (int e = 0; e < NE; e++) out_logits[(size_t)t * NE + e] = acc[e];
        }
        int e1 = 0; float v1 = acc[0];
#pragma unroll
        for (int e = 1; e < NE; e++) if (acc[e] > v1) { v1 = acc[e]; e1 = e; }
        int e2 = -1; float v2 = -1e30f;
#pragma unroll
        for (int e = 0; e < NE; e++) if (e != e1 && acc[e] > v2) { v2 = acc[e]; e2 = e; }
        float s1 = 1.f / (1.f + __expf(-v1));
        float s2 = 1.f / (1.f + __expf(-v2));
        g_tope[t * 2 + 0] = e1; g_tops[t * 2 + 0] = s1;
        g_tope[t * 2 + 1] = e2; g_tops[t * 2 + 1] = s2;
        atomicAdd(&g_cnt[e1], 1);
        atomicAdd(&g_cnt[e2], 1);
    }
}

// ---------------- scatter ----------------
__global__ __launch_bounds__(256) void k_scatter() {
    __shared__ int lcnt[NE], lbase[NE];
    int tid = threadIdx.x;
    if (tid < NE) lcnt[tid] = 0;
    __syncthreads();
    int t = blockIdx.x * 256 + tid;
    int e0 = g_tope[2 * t], e1 = g_tope[2 * t + 1];
    float s0 = g_tops[2 * t], s1 = g_tops[2 * t + 1];
    int p0 = atomicAdd(&lcnt[e0], 1);
    int p1 = atomicAdd(&lcnt[e1], 1);
    __syncthreads();
    if (tid < NE) lbase[tid] = atomicAdd(&g_cur[tid], lcnt[tid]);
    __syncthreads();
    int r0 = g_off[e0] + lbase[e0] + p0;
    int r1 = g_off[e1] + lbase[e1] + p1;
    g_row_tok[r0] = t; g_row_sc[r0] = s0; g_row_slot[r0] = 0;
    g_row_tok[r1] = t; g_row_sc[r1] = s1; g_row_slot[r1] = 1;
}

// ---------------- GEMM kernels ----------------
__global__ __launch_bounds__(256, 2) void tc_gu_routed() {
    int e = blockIdx.y >> 5, rt = blockIdx.y & 31;
    int cnt = g_cnt[e];
    int row0 = rt * 128;
    if (row0 >= cnt) return;
    int base = g_off[e];

    extern __shared__ char sm[];
    uint32_t sbu = smem_u32(sm);
    int t = threadIdx.x, rb = t >> 1, half = t & 1;
    int rr = base + min(row0 + rb, cnt - 1);
    size_t arow = (size_t)g_row_tok[rr] * HDIM + half * 16;
    int n0 = blockIdx.x * 128;
    const __half* bp = g_wgu + (size_t)e * 2 * IDIM * HDIM + (size_t)(n0 + rb) * HDIM + half * 16;

    float acc[2][8][4];
#pragma unroll
    for (int a = 0; a < 2; a++)
#pragma unroll
        for (int b = 0; b < 8; b++)
#pragma unroll
            for (int q = 0; q < 4; q++) acc[a][b][q] = 0.f;

    gemm_core(g_x_h + arow, g_x_l + arow, bp, HDIM, sm, sbu, acc);

    int lane = t & 31, wid = t >> 5, g = lane >> 2, tg = lane & 3;
    int wm0 = (wid >> 1) * 32;
    int jb = n0 / 2 + ((wid & 1) * 64) / 2 + tg;
#pragma unroll
    for (int mi = 0; mi < 2; mi++)
#pragma unroll
        for (int dq = 0; dq < 2; dq++) {
            int rl = wm0 + mi * 16 + g + dq * 8;
            if (row0 + rl < cnt) {
                int grow = base + row0 + rl;
                float sc = g_row_sc[grow];
                __half* dh = g_act_h + (size_t)grow * IDIM;
                __half* dl = g_act_l + (size_t)grow * IDIM;
#pragma unroll
                for (int nj = 0; nj < 8; nj++) {
                    float v = silu_mul(sc * acc[mi][nj][dq * 2], sc * acc[mi][nj][dq * 2 + 1]);
                    __half h = __float2half_rn(v);
                    dh[jb + nj * 4] = h;
                    dl[jb + nj * 4] = __float2half_rn(v - __half2float(h));
                }
            }
        }
}

__global__ __launch_bounds__(256, 2) void tc_dn_routed() {
    int e = blockIdx.y >> 5, rt = blockIdx.y & 31;
    int cnt = g_cnt[e];
    int row0 = rt * 128;
    if (row0 >= cnt) return;
    int base = g_off[e];

    extern __shared__ char sm[];
    uint32_t sbu = smem_u32(sm);
    int t = threadIdx.x, rb = t >> 1, half = t & 1;
    size_t arow = (size_t)(base + min(row0 + rb, cnt - 1)) * IDIM + half * 16;
    int n0 = blockIdx.x * 128;
    const __half* bp = g_wdn + (size_t)e * HDIM * IDIM + (size_t)(n0 + rb) * IDIM + half * 16;

    float acc[2][8][4];
#pragma unroll
    for (int a = 0; a < 2; a++)
#pragma unroll
        for (int b = 0; b < 8; b++)
#pragma unroll
            for (int q = 0; q < 4; q++) acc[a][b][q] = 0.f;

    gemm_core(g_act_h + arow, g_act_l + arow, bp, IDIM, sm, sbu, acc);

    int lane = t & 31, wid = t >> 5, g = lane >> 2, tg = lane & 3;
    int wm0 = (wid >> 1) * 32, wn0 = (wid & 1) * 64;
    int colb = n0 + wn0 + tg * 2;
#pragma unroll
    for (int mi = 0; mi < 2; mi++)
#pragma unroll
        for (int dq = 0; dq < 2; dq++) {
            int rl = wm0 + mi * 16 + g + dq * 8;
            if (row0 + rl < cnt) {
                int grow = base + row0 + rl;
                int tok = g_row_tok[grow], slot = g_row_slot[grow];
                float* dst = g_partial[slot] + (size_t)tok * HDIM;
#pragma unroll
                for (int nj = 0; nj < 8; nj++) {
                    float2 v = {acc[mi][nj][dq * 2], acc[mi][nj][dq * 2 + 1]};
                    *(float2*)&dst[colb + nj * 8] = v;
                }
            }
        }
}

__global__ __launch_bounds__(256, 2) void tc_gu_shared() {
    int row0 = blockIdx.y * 128;
    int n0 = blockIdx.x * 128;

    extern __shared__ char sm[];
    uint32_t sbu = smem_u32(sm);
    int t = threadIdx.x, rb = t >> 1, half = t & 1;
    size_t arow = (size_t)(row0 + rb) * HDIM + half * 16;
    const __half* bp = g_wsg + (size_t)(n0 + rb) * HDIM + half * 16;

    float acc[2][8][4];
#pragma unroll
    for (int a = 0; a < 2; a++)
#pragma unroll
        for (int b = 0; b < 8; b++)
#pragma unroll
            for (int q = 0; q < 4; q++) acc[a][b][q] = 0.f;

    gemm_core(g_x_h + arow, g_x_l + arow, bp, HDIM, sm, sbu, acc);

    int lane = t & 31, wid = t >> 5, g = lane >> 2, tg = lane & 3;
    int wm0 = (wid >> 1) * 32;
    int jb = n0 / 2 + ((wid & 1) * 64) / 2 + tg;
#pragma unroll
    for (int mi = 0; mi < 2; mi++)
#pragma unroll
        for (int dq = 0; dq < 2; dq++) {
            int rl = wm0 + mi * 16 + g + dq * 8;
            __half* dh = g_acts_h + (size_t)(row0 + rl) * IDIM;
            __half* dl = g_acts_l + (size_t)(row0 + rl) * IDIM;
#pragma unroll
            for (int nj = 0; nj < 8; nj++) {
                float v = silu_mul(acc[mi][nj][dq * 2], acc[mi][nj][dq * 2 + 1]);
                __half h = __float2half_rn(v);
                dh[jb + nj * 4] = h;
                dl[jb + nj * 4] = __float2half_rn(v - __half2float(h));
            }
        }
}

__global__ __launch_bounds__(256, 2) void tc_dn_shared(float* __restrict__ out) {
    int row0 = blockIdx.y * 128;
    int n0 = blockIdx.x * 128;

    extern __shared__ char sm[];
    uint32_t sbu = smem_u32(sm);
    int t = threadIdx.x, rb = t >> 1, half = t & 1;
    size_t arow = (size_t)(row0 + rb) * IDIM + half * 16;
    const __half* bp = g_wsd + (size_t)(n0 + rb) * IDIM + half * 16;

    float acc[2][8][4];
#pragma unroll
    for (int a = 0; a < 2; a++)
#pragma unroll
        for (int b = 0; b < 8; b++)
#pragma unroll
            for (int q = 0; q < 4; q++) acc[a][b][q] = 0.f;

    gemm_core(g_acts_h + arow, g_acts_l + arow, bp, IDIM, sm, sbu, acc);

    int lane = t & 31, wid = t >> 5, g = lane >> 2, tg = lane & 3;
    int wm0 = (wid >> 1) * 32, wn0 = (wid & 1) * 64;
    int colb = n0 + wn0 + tg * 2;
#pragma unroll
    for (int mi = 0; mi < 2; mi++)
#pragma unroll
        for (int dq = 0; dq < 2; dq++) {
            int row = row0 + wm0 + mi * 16 + g + dq * 8;
            size_t rbase = (size_t)row * HDIM;
#pragma unroll
            for (int nj = 0; nj < 8; nj++) {
                size_t idx = rbase + colb + nj * 8;
                float2 p0 = *(const float2*)&g_partial[0][idx];
                float2 p1 = *(const float2*)&g_partial[1][idx];
                float2 v;
                v.x = acc[mi][nj][dq * 2] + p0.x + p1.x;
                v.y = acc[mi][nj][dq * 2 + 1] + p0.y + p1.y;
                *(float2*)&out[idx] = v;
            }
        }
}

// ---------------- launch ----------------
extern "C" void kernel_launch(void* const* d_in, const int* in_sizes, int n_in,
                              void* d_out, int out_size) {
    const float* x     = (const float*)d_in[0];   // [T, H]
    const float* rw    = (const float*)d_in[1];   // [E, H]
    const float* gup   = (const float*)d_in[2];   // [E, H, 2I]
    const float* dwn   = (const float*)d_in[3];   // [E, I, H]
    const float* sgate = (const float*)d_in[4];   // [I, H]
    const float* sup   = (const float*)d_in[5];   // [I, H]
    const float* sdown = (const float*)d_in[6];   // [H, I]
    float* out = (float*)d_out;

    float* out_logits = nullptr;
    if (out_size >= TTOK * HDIM + TTOK * NE) out_logits = out + (size_t)TTOK * HDIM;

    cudaFuncSetAttribute(tc_gu_routed, cudaFuncAttributeMaxDynamicSharedMemorySize, SMEM_GEMM);
    cudaFuncSetAttribute(tc_dn_routed, cudaFuncAttributeMaxDynamicSharedMemorySize, SMEM_GEMM);
    cudaFuncSetAttribute(tc_gu_shared, cudaFuncAttributeMaxDynamicSharedMemorySize, SMEM_GEMM);
    cudaFuncSetAttribute(tc_dn_shared, cudaFuncAttributeMaxDynamicSharedMemorySize, SMEM_GEMM);

    k_init<<<1, 32>>>();
    k_router<<<TTOK / 4, 128>>>(x, rw, out_logits);
    k_prefix<<<1, 32>>>();
    k_scatter<<<TTOK / 256, 256>>>();

    // activation + weight conversions (fp16 / fp16 hi-lo, mma-friendly layouts)
    k_cvt_x<<<(TTOK * HDIM) / 256, 256>>>(x);
    k_cvt_gup<<<dim3(2 * IDIM / 32, HDIM / 32, NE), dim3(32, 8)>>>(gup);
    k_cvt_dwn<<<dim3(HDIM / 32, IDIM / 32, NE), dim3(32, 8)>>>(dwn);
    k_cvt_sharedgu<<<(IDIM * HDIM) / 256, 256>>>(sgate, sup);
    k_cvt_shareddn<<<(HDIM * IDIM) / 256, 256>>>(sdown);

    tc_gu_routed<<<dim3(2 * IDIM / 128, NE * 32), 256, SMEM_GEMM>>>();
    tc_dn_routed<<<dim3(HDIM / 128, NE * 32), 256, SMEM_GEMM>>>();
    tc_gu_shared<<<dim3(2 * IDIM / 128, TTOK / 128), 256, SMEM_GEMM>>>();
    tc_dn_shared<<<dim3(HDIM / 128, TTOK / 128), 256, SMEM_GEMM>>>(out);
}

// round 8
// speedup vs baseline: 4.0233x; 1.4653x over previous
#include <cuda_runtime.h>
#include <cuda_fp16.h>
#include <stdint.h>
#include <math.h>

// Problem constants
#define TTOK 4096
#define HDIM 1024
#define IDIM 2048
#define NE   8
#define NPAIR (TTOK * 2)

// GEMM config: 128x128 CTA tile, 8 warps (4M x 2N), KC=32, double-buffered
#define KC 32
#define A_PITCH 80               // bytes per smem row (40 fp16, conflict-free frag loads)
#define SM_AH 0
#define SM_BH 10240
#define SM_STAGE 20480
#define SMEM_GEMM (2 * SM_STAGE) // 40960 B

// ---------------- scratch (static __device__ — no allocation) ----------------
__device__ __half g_x[(size_t)TTOK * HDIM];             // x fp16
__device__ __half g_act[(size_t)NPAIR * IDIM];          // routed swiglu act fp16
__device__ __half g_acts[(size_t)TTOK * IDIM];          // shared swiglu act fp16
__device__ float g_partial[2][(size_t)TTOK * HDIM];     // per-slot routed outputs
__device__ int   g_row_tok[NPAIR];
__device__ float g_row_sc[NPAIR];
__device__ int   g_row_slot[NPAIR];
__device__ int   g_tope[NPAIR];
__device__ float g_tops[NPAIR];
__device__ int   g_cnt[NE];
__device__ int   g_off[NE];
__device__ int   g_cur[NE];

// fp16 weights, [n][k] col-major-for-mma layouts
__device__ __half g_wgu[(size_t)NE * 2 * IDIM * HDIM];   // interleaved gate/up rows
__device__ __half g_wdn[(size_t)NE * HDIM * IDIM];       // [H][I]
__device__ __half g_wsg[(size_t)2 * IDIM * HDIM];        // shared gate/up interleaved
__device__ __half g_wsd[(size_t)HDIM * IDIM];            // [H][I]

// ---------------- small helpers ----------------
__device__ __forceinline__ uint32_t smem_u32(const void* p) {
    uint32_t a;
    asm("{ .reg .u64 t; cvta.to.shared.u64 t, %1; cvt.u32.u64 %0, t; }" : "=r"(a) : "l"(p));
    return a;
}
__device__ __forceinline__ void cpa16(uint32_t saddr, const void* g) {
    asm volatile("cp.async.ca.shared.global [%0], [%1], 16;" :: "r"(saddr), "l"(g));
}
__device__ __forceinline__ void cpa_commit() {
    asm volatile("cp.async.commit_group;" ::: "memory");
}
__device__ __forceinline__ void cpa_wait0() {
    asm volatile("cp.async.wait_group 0;" ::: "memory");
}
__device__ __forceinline__ float silu_mul(float g, float u) {
    return u * g / (1.f + __expf(-g));
}
__device__ __forceinline__ void mma16816(float d[4], uint32_t a0, uint32_t a1, uint32_t a2,
                                         uint32_t a3, uint32_t b0, uint32_t b1) {
    asm volatile(
        "mma.sync.aligned.m16n8k16.row.col.f32.f16.f16.f32 "
        "{%0,%1,%2,%3}, {%4,%5,%6,%7}, {%8,%9}, {%0,%1,%2,%3};"
        : "+f"(d[0]), "+f"(d[1]), "+f"(d[2]), "+f"(d[3])
        : "r"(a0), "r"(a1), "r"(a2), "r"(a3), "r"(b0), "r"(b1));
}

// ---------------- GEMM core: C[128x128] += A * B  (fp16 x fp16, f32 accum) ----------------
// a_p/b_p: per-thread source pointers, already offset to (row rb, half*16).
__device__ __forceinline__ void gemm_core(const __half* __restrict__ a_p,
                                          const __half* __restrict__ b_p,
                                          int Ktot, char* sm, uint32_t sbu,
                                          float acc[2][8][4]) {
    const int t = threadIdx.x;
    const int lane = t & 31, wid = t >> 5;
    const int g = lane >> 2, tg = lane & 3;
    const int wm0 = (wid >> 1) * 32, wn0 = (wid & 1) * 64;
    const int rb = t >> 1, half = t & 1;
    const int nc = Ktot / KC;

    const uint32_t sA = sbu + SM_AH + rb * A_PITCH + half * 32;
    const uint32_t sB = sbu + SM_BH + rb * A_PITCH + half * 32;

    // prologue: chunk 0 into stage 0
    cpa16(sA, a_p); cpa16(sA + 16, a_p + 8);
    cpa16(sB, b_p); cpa16(sB + 16, b_p + 8);
    cpa_commit();

    for (int c = 0; c < nc; c++) {
        const int s = c & 1;
        cpa_wait0();
        __syncthreads();
        if (c + 1 < nc) {
            const uint32_t so = (1 - s) * SM_STAGE;
            const __half* pa = a_p + (c + 1) * KC;
            const __half* pb = b_p + (c + 1) * KC;
            cpa16(sA + so, pa); cpa16(sA + so + 16, pa + 8);
            cpa16(sB + so, pb); cpa16(sB + so + 16, pb + 8);
            cpa_commit();
        }
        const char* pA = sm + s * SM_STAGE + SM_AH;
        const char* pB = sm + s * SM_STAGE + SM_BH;
#pragma unroll
        for (int ks = 0; ks < 2; ks++) {
            uint32_t ah[2][4];
#pragma unroll
            for (int mi = 0; mi < 2; mi++) {
                int rbase = (wm0 + mi * 16 + g) * A_PITCH + ks * 32 + tg * 4;
                ah[mi][0] = *(const uint32_t*)(pA + rbase);
                ah[mi][1] = *(const uint32_t*)(pA + rbase + 8 * A_PITCH);
                ah[mi][2] = *(const uint32_t*)(pA + rbase + 16);
                ah[mi][3] = *(const uint32_t*)(pA + rbase + 8 * A_PITCH + 16);
            }
#pragma unroll
            for (int nj = 0; nj < 8; nj++) {
                int nb = (wn0 + nj * 8 + g) * A_PITCH + ks * 32 + tg * 4;
                uint32_t b0 = *(const uint32_t*)(pB + nb);
                uint32_t b1 = *(const uint32_t*)(pB + nb + 16);
#pragma unroll
                for (int mi = 0; mi < 2; mi++)
                    mma16816(acc[mi][nj], ah[mi][0], ah[mi][1], ah[mi][2], ah[mi][3], b0, b1);
            }
        }
    }
}

// ---------------- conversions ----------------
__global__ void k_cvt_x(const float* __restrict__ x) {
    size_t id = (size_t)blockIdx.x * 256 + threadIdx.x;
    g_x[id] = __float2half_rn(x[id]);
}

// transpose-convert: src fp32 [K][N] (per-expert) -> dst fp16 [n'][K]
__device__ __forceinline__ void cvt_T_body(const float* __restrict__ s,
                                           __half* __restrict__ oh,
                                           int K, int N, int remap_half) {
    __shared__ float tile[32][33];
    int c0 = blockIdx.x * 32;
    int k0 = blockIdx.y * 32;
    int tx = threadIdx.x, ty = threadIdx.y;
#pragma unroll
    for (int i = 0; i < 4; i++) {
        int k = ty + i * 8;
        tile[k][tx] = s[(size_t)(k0 + k) * N + c0 + tx];
    }
    __syncthreads();
#pragma unroll
    for (int i = 0; i < 4; i++) {
        int cc = c0 + ty + i * 8;
        int n = remap_half ? (2 * (cc % remap_half) + cc / remap_half) : cc;
        oh[(size_t)n * K + k0 + tx] = __float2half_rn(tile[tx][ty + i * 8]);
    }
}

__global__ void k_cvt_gup(const float* __restrict__ gup) {
    int e = blockIdx.z;
    cvt_T_body(gup + (size_t)e * HDIM * 2 * IDIM,
               g_wgu + (size_t)e * 2 * IDIM * HDIM, HDIM, 2 * IDIM, IDIM);
}
__global__ void k_cvt_dwn(const float* __restrict__ dwn) {
    int e = blockIdx.z;
    cvt_T_body(dwn + (size_t)e * IDIM * HDIM,
               g_wdn + (size_t)e * HDIM * IDIM, IDIM, HDIM, 0);
}
__global__ void k_cvt_sharedgu(const float* __restrict__ gw, const float* __restrict__ uw) {
    size_t id = (size_t)blockIdx.x * 256 + threadIdx.x;   // over I*H
    int j = (int)(id / HDIM), k = (int)(id % HDIM);
    g_wsg[(size_t)(2 * j) * HDIM + k]     = __float2half_rn(gw[id]);
    g_wsg[(size_t)(2 * j + 1) * HDIM + k] = __float2half_rn(uw[id]);
}
__global__ void k_cvt_shareddn(const float* __restrict__ dw) {
    size_t id = (size_t)blockIdx.x * 256 + threadIdx.x;   // over H*I
    g_wsd[id] = __float2half_rn(dw[id]);
}

// ---------------- tiny control kernels ----------------
__global__ void k_init() { if (threadIdx.x < NE) g_cnt[threadIdx.x] = 0; }
__global__ void k_prefix() {
    if (threadIdx.x == 0) {
        int s = 0;
        for (int e = 0; e < NE; e++) { g_off[e] = s; s += g_cnt[e]; }
    }
    if (threadIdx.x < NE) g_cur[threadIdx.x] = 0;
}

// ---------------- router ----------------
__global__ __launch_bounds__(128) void k_router(const float* __restrict__ x,
                                                const float* __restrict__ rw,
                                                float* __restrict__ out_logits) {
    int warp = threadIdx.x >> 5, lane = threadIdx.x & 31;
    int t = blockIdx.x * 4 + warp;
    if (t >= TTOK) return;
    const float* xr = x + (size_t)t * HDIM;
    float acc[NE];
#pragma unroll
    for (int e = 0; e < NE; e++) acc[e] = 0.f;
    for (int i = lane; i < HDIM; i += 32) {
        float xv = xr[i];
#pragma unroll
        for (int e = 0; e < NE; e++) acc[e] = fmaf(xv, rw[e * HDIM + i], acc[e]);
    }
#pragma unroll
    for (int e = 0; e < NE; e++) {
#pragma unroll
        for (int o = 16; o > 0; o >>= 1) acc[e] += __shfl_xor_sync(0xFFFFFFFFu, acc[e], o);
    }
    if (lane == 0) {
        if (out_logits) {
#pragma unroll
            for (int e = 0; e < NE; e++) out_logits[(size_t)t * NE + e] = acc[e];
        }
        int e1 = 0; float v1 = acc[0];
#pragma unroll
        for (int e = 1; e < NE; e++) if (acc[e] > v1) { v1 = acc[e]; e1 = e; }
        int e2 = -1; float v2 = -1e30f;
#pragma unroll
        for (int e = 0; e < NE; e++) if (e != e1 && acc[e] > v2) { v2 = acc[e]; e2 = e; }
        float s1 = 1.f / (1.f + __expf(-v1));
        float s2 = 1.f / (1.f + __expf(-v2));
        g_tope[t * 2 + 0] = e1; g_tops[t * 2 + 0] = s1;
        g_tope[t * 2 + 1] = e2; g_tops[t * 2 + 1] = s2;
        atomicAdd(&g_cnt[e1], 1);
        atomicAdd(&g_cnt[e2], 1);
    }
}

// ---------------- scatter ----------------
__global__ __launch_bounds__(256) void k_scatter() {
    __shared__ int lcnt[NE], lbase[NE];
    int tid = threadIdx.x;
    if (tid < NE) lcnt[tid] = 0;
    __syncthreads();
    int t = blockIdx.x * 256 + tid;
    int e0 = g_tope[2 * t], e1 = g_tope[2 * t + 1];
    float s0 = g_tops[2 * t], s1 = g_tops[2 * t + 1];
    int p0 = atomicAdd(&lcnt[e0], 1);
    int p1 = atomicAdd(&lcnt[e1], 1);
    __syncthreads();
    if (tid < NE) lbase[tid] = atomicAdd(&g_cur[tid], lcnt[tid]);
    __syncthreads();
    int r0 = g_off[e0] + lbase[e0] + p0;
    int r1 = g_off[e1] + lbase[e1] + p1;
    g_row_tok[r0] = t; g_row_sc[r0] = s0; g_row_slot[r0] = 0;
    g_row_tok[r1] = t; g_row_sc[r1] = s1; g_row_slot[r1] = 1;
}

// ---------------- GEMM kernels ----------------
__global__ __launch_bounds__(256, 2) void tc_gu_routed() {
    int e = blockIdx.y >> 5, rt = blockIdx.y & 31;
    int cnt = g_cnt[e];
    int row0 = rt * 128;
    if (row0 >= cnt) return;
    int base = g_off[e];

    extern __shared__ char sm[];
    uint32_t sbu = smem_u32(sm);
    int t = threadIdx.x, rb = t >> 1, half = t & 1;
    int rr = base + min(row0 + rb, cnt - 1);
    const __half* ap = g_x + (size_t)g_row_tok[rr] * HDIM + half * 16;
    int n0 = blockIdx.x * 128;
    const __half* bp = g_wgu + (size_t)e * 2 * IDIM * HDIM + (size_t)(n0 + rb) * HDIM + half * 16;

    float acc[2][8][4];
#pragma unroll
    for (int a = 0; a < 2; a++)
#pragma unroll
        for (int b = 0; b < 8; b++)
#pragma unroll
            for (int q = 0; q < 4; q++) acc[a][b][q] = 0.f;

    gemm_core(ap, bp, HDIM, sm, sbu, acc);

    int lane = t & 31, wid = t >> 5, g = lane >> 2, tg = lane & 3;
    int wm0 = (wid >> 1) * 32;
    int jb = n0 / 2 + ((wid & 1) * 64) / 2 + tg;
#pragma unroll
    for (int mi = 0; mi < 2; mi++)
#pragma unroll
        for (int dq = 0; dq < 2; dq++) {
            int rl = wm0 + mi * 16 + g + dq * 8;
            if (row0 + rl < cnt) {
                int grow = base + row0 + rl;
                float sc = g_row_sc[grow];
                __half* dh = g_act + (size_t)grow * IDIM;
#pragma unroll
                for (int nj = 0; nj < 8; nj++) {
                    float v = silu_mul(sc * acc[mi][nj][dq * 2], sc * acc[mi][nj][dq * 2 + 1]);
                    dh[jb + nj * 4] = __float2half_rn(v);
                }
            }
        }
}

__global__ __launch_bounds__(256, 2) void tc_dn_routed() {
    int e = blockIdx.y >> 5, rt = blockIdx.y & 31;
    int cnt = g_cnt[e];
    int row0 = rt * 128;
    if (row0 >= cnt) return;
    int base = g_off[e];

    extern __shared__ char sm[];
    uint32_t sbu = smem_u32(sm);
    int t = threadIdx.x, rb = t >> 1, half = t & 1;
    const __half* ap = g_act + (size_t)(base + min(row0 + rb, cnt - 1)) * IDIM + half * 16;
    int n0 = blockIdx.x * 128;
    const __half* bp = g_wdn + (size_t)e * HDIM * IDIM + (size_t)(n0 + rb) * IDIM + half * 16;

    float acc[2][8][4];
#pragma unroll
    for (int a = 0; a < 2; a++)
#pragma unroll
        for (int b = 0; b < 8; b++)
#pragma unroll
            for (int q = 0; q < 4; q++) acc[a][b][q] = 0.f;

    gemm_core(ap, bp, IDIM, sm, sbu, acc);

    int lane = t & 31, wid = t >> 5, g = lane >> 2, tg = lane & 3;
    int wm0 = (wid >> 1) * 32, wn0 = (wid & 1) * 64;
    int colb = n0 + wn0 + tg * 2;
#pragma unroll
    for (int mi = 0; mi < 2; mi++)
#pragma unroll
        for (int dq = 0; dq < 2; dq++) {
            int rl = wm0 + mi * 16 + g + dq * 8;
            if (row0 + rl < cnt) {
                int grow = base + row0 + rl;
                int tok = g_row_tok[grow], slot = g_row_slot[grow];
                float* dst = g_partial[slot] + (size_t)tok * HDIM;
#pragma unroll
                for (int nj = 0; nj < 8; nj++) {
                    float2 v = {acc[mi][nj][dq * 2], acc[mi][nj][dq * 2 + 1]};
                    *(float2*)&dst[colb + nj * 8] = v;
                }
            }
        }
}

__global__ __launch_bounds__(256, 2) void tc_gu_shared() {
    int row0 = blockIdx.y * 128;
    int n0 = blockIdx.x * 128;

    extern __shared__ char sm[];
    uint32_t sbu = smem_u32(sm);
    int t = threadIdx.x, rb = t >> 1, half = t & 1;
    const __half* ap = g_x + (size_t)(row0 + rb) * HDIM + half * 16;
    const __half* bp = g_wsg + (size_t)(n0 + rb) * HDIM + half * 16;

    float acc[2][8][4];
#pragma unroll
    for (int a = 0; a < 2; a++)
#pragma unroll
        for (int b = 0; b < 8; b++)
#pragma unroll
            for (int q = 0; q < 4; q++) acc[a][b][q] = 0.f;

    gemm_core(ap, bp, HDIM, sm, sbu, acc);

    int lane = t & 31, wid = t >> 5, g = lane >> 2, tg = lane & 3;
    int wm0 = (wid >> 1) * 32;
    int jb = n0 / 2 + ((wid & 1) * 64) / 2 + tg;
#pragma unroll
    for (int mi = 0; mi < 2; mi++)
#pragma unroll
        for (int dq = 0; dq < 2; dq++) {
            int rl = wm0 + mi * 16 + g + dq * 8;
            __half* dh = g_acts + (size_t)(row0 + rl) * IDIM;
#pragma unroll
            for (int nj = 0; nj < 8; nj++) {
                float v = silu_mul(acc[mi][nj][dq * 2], acc[mi][nj][dq * 2 + 1]);
                dh[jb + nj * 4] = __float2half_rn(v);
            }
        }
}

__global__ __launch_bounds__(256, 2) void tc_dn_shared(float* __restrict__ out) {
    int row0 = blockIdx.y * 128;
    int n0 = blockIdx.x * 128;

    extern __shared__ char sm[];
    uint32_t sbu = smem_u32(sm);
    int t = threadIdx.x, rb = t >> 1, half = t & 1;
    const __half* ap = g_acts + (size_t)(row0 + rb) * IDIM + half * 16;
    const __half* bp = g_wsd + (size_t)(n0 + rb) * IDIM + half * 16;

    float acc[2][8][4];
#pragma unroll
    for (int a = 0; a < 2; a++)
#pragma unroll
        for (int b = 0; b < 8; b++)
#pragma unroll
            for (int q = 0; q < 4; q++) acc[a][b][q] = 0.f;

    gemm_core(ap, bp, IDIM, sm, sbu, acc);

    int lane = t & 31, wid = t >> 5, g = lane >> 2, tg = lane & 3;
    int wm0 = (wid >> 1) * 32, wn0 = (wid & 1) * 64;
    int colb = n0 + wn0 + tg * 2;
#pragma unroll
    for (int mi = 0; mi < 2; mi++)
#pragma unroll
        for (int dq = 0; dq < 2; dq++) {
            int row = row0 + wm0 + mi * 16 + g + dq * 8;
            size_t rbase = (size_t)row * HDIM;
#pragma unroll
            for (int nj = 0; nj < 8; nj++) {
                size_t idx = rbase + colb + nj * 8;
                float2 p0 = *(const float2*)&g_partial[0][idx];
                float2 p1 = *(const float2*)&g_partial[1][idx];
                float2 v;
                v.x = acc[mi][nj][dq * 2] + p0.x + p1.x;
                v.y = acc[mi][nj][dq * 2 + 1] + p0.y + p1.y;
                *(float2*)&out[idx] = v;
            }
        }
}

// ---------------- launch ----------------
extern "C" void kernel_launch(void* const* d_in, const int* in_sizes, int n_in,
                              void* d_out, int out_size) {
    const float* x     = (const float*)d_in[0];   // [T, H]
    const float* rw    = (const float*)d_in[1];   // [E, H]
    const float* gup   = (const float*)d_in[2];   // [E, H, 2I]
    const float* dwn   = (const float*)d_in[3];   // [E, I, H]
    const float* sgate = (const float*)d_in[4];   // [I, H]
    const float* sup   = (const float*)d_in[5];   // [I, H]
    const float* sdown = (const float*)d_in[6];   // [H, I]
    float* out = (float*)d_out;

    float* out_logits = nullptr;
    if (out_size >= TTOK * HDIM + TTOK * NE) out_logits = out + (size_t)TTOK * HDIM;

    cudaFuncSetAttribute(tc_gu_routed, cudaFuncAttributeMaxDynamicSharedMemorySize, SMEM_GEMM);
    cudaFuncSetAttribute(tc_dn_routed, cudaFuncAttributeMaxDynamicSharedMemorySize, SMEM_GEMM);
    cudaFuncSetAttribute(tc_gu_shared, cudaFuncAttributeMaxDynamicSharedMemorySize, SMEM_GEMM);
    cudaFuncSetAttribute(tc_dn_shared, cudaFuncAttributeMaxDynamicSharedMemorySize, SMEM_GEMM);

    k_init<<<1, 32>>>();
    k_router<<<TTOK / 4, 128>>>(x, rw, out_logits);
    k_prefix<<<1, 32>>>();
    k_scatter<<<TTOK / 256, 256>>>();

    // activation + weight conversions (fp16, mma-friendly layouts)
    k_cvt_x<<<(TTOK * HDIM) / 256, 256>>>(x);
    k_cvt_gup<<<dim3(2 * IDIM / 32, HDIM / 32, NE), dim3(32, 8)>>>(gup);
    k_cvt_dwn<<<dim3(HDIM / 32, IDIM / 32, NE), dim3(32, 8)>>>(dwn);
    k_cvt_sharedgu<<<(IDIM * HDIM) / 256, 256>>>(sgate, sup);
    k_cvt_shareddn<<<(HDIM * IDIM) / 256, 256>>>(sdown);

    tc_gu_routed<<<dim3(2 * IDIM / 128, NE * 32), 256, SMEM_GEMM>>>();
    tc_dn_routed<<<dim3(HDIM / 128, NE * 32), 256, SMEM_GEMM>>>();
    tc_gu_shared<<<dim3(2 * IDIM / 128, TTOK / 128), 256, SMEM_GEMM>>>();
    tc_dn_shared<<<dim3(HDIM / 128, TTOK / 128), 256, SMEM_GEMM>>>(out);
}

// round 9
// speedup vs baseline: 4.2674x; 1.0607x over previous
#include <cuda_runtime.h>
#include <cuda_fp16.h>
#include <stdint.h>
#include <math.h>

// Problem constants
#define TTOK 4096
#define HDIM 1024
#define IDIM 2048
#define NE   8
#define NPAIR (TTOK * 2)

// GEMM config: 128x128 CTA tile, 8 warps (4M x 2N), KC=64, double-buffered
#define KC 64
#define A_PITCH 144              // bytes per smem row (64 fp16 + pad, conflict-free frags)
#define SM_A 0
#define SM_B (128 * A_PITCH)                 // 18432
#define SM_STAGE (2 * 128 * A_PITCH)         // 36864
#define SMEM_GEMM (2 * SM_STAGE)             // 73728 -> 2 CTAs/SM

// ---------------- scratch (static __device__ — no allocation) ----------------
__device__ __half g_x[(size_t)TTOK * HDIM];             // x fp16
__device__ __half g_act[(size_t)NPAIR * IDIM];          // routed swiglu act fp16
__device__ __half g_acts[(size_t)TTOK * IDIM];          // shared swiglu act fp16
__device__ float g_partial[2][(size_t)TTOK * HDIM];     // per-slot routed outputs
__device__ int   g_row_tok[NPAIR];
__device__ float g_row_sc[NPAIR];
__device__ int   g_row_slot[NPAIR];
__device__ int   g_tope[NPAIR];
__device__ float g_tops[NPAIR];
__device__ int   g_cnt[NE];
__device__ int   g_off[NE];
__device__ int   g_cur[NE];

// fp16 weights, [n][k] col-major-for-mma layouts
__device__ __half g_wgu[(size_t)NE * 2 * IDIM * HDIM];   // interleaved gate/up rows
__device__ __half g_wdn[(size_t)NE * HDIM * IDIM];       // [H][I]
__device__ __half g_wsg[(size_t)2 * IDIM * HDIM];        // shared gate/up interleaved
__device__ __half g_wsd[(size_t)HDIM * IDIM];            // [H][I]

// ---------------- small helpers ----------------
__device__ __forceinline__ uint32_t smem_u32(const void* p) {
    uint32_t a;
    asm("{ .reg .u64 t; cvta.to.shared.u64 t, %1; cvt.u32.u64 %0, t; }" : "=r"(a) : "l"(p));
    return a;
}
__device__ __forceinline__ void cpa16(uint32_t saddr, const void* g) {
    asm volatile("cp.async.ca.shared.global [%0], [%1], 16;" :: "r"(saddr), "l"(g));
}
__device__ __forceinline__ void cpa_commit() {
    asm volatile("cp.async.commit_group;" ::: "memory");
}
__device__ __forceinline__ void cpa_wait0() {
    asm volatile("cp.async.wait_group 0;" ::: "memory");
}
__device__ __forceinline__ float silu_mul(float g, float u) {
    return u * g / (1.f + __expf(-g));
}
__device__ __forceinline__ void mma16816(float d[4], uint32_t a0, uint32_t a1, uint32_t a2,
                                         uint32_t a3, uint32_t b0, uint32_t b1) {
    asm volatile(
        "mma.sync.aligned.m16n8k16.row.col.f32.f16.f16.f32 "
        "{%0,%1,%2,%3}, {%4,%5,%6,%7}, {%8,%9}, {%0,%1,%2,%3};"
        : "+f"(d[0]), "+f"(d[1]), "+f"(d[2]), "+f"(d[3])
        : "r"(a0), "r"(a1), "r"(a2), "r"(a3), "r"(b0), "r"(b1));
}

// ---------------- GEMM core: C[128x128] += A * B  (fp16 x fp16, f32 accum) ----------------
// a_p/b_p: per-thread source pointers, already offset to (row rb, half*32 elems).
__device__ __forceinline__ void gemm_core(const __half* __restrict__ a_p,
                                          const __half* __restrict__ b_p,
                                          int Ktot, char* sm, uint32_t sbu,
                                          float acc[2][8][4]) {
    const int t = threadIdx.x;
    const int lane = t & 31, wid = t >> 5;
    const int g = lane >> 2, tg = lane & 3;
    const int wm0 = (wid >> 1) * 32, wn0 = (wid & 1) * 64;
    const int rb = t >> 1;
    const int nc = Ktot / KC;

    const uint32_t sA = sbu + SM_A + rb * A_PITCH + (t & 1) * 64;
    const uint32_t sB = sbu + SM_B + rb * A_PITCH + (t & 1) * 64;

    // prologue: chunk 0 into stage 0
#pragma unroll
    for (int q = 0; q < 4; q++) {
        cpa16(sA + q * 16, a_p + q * 8);
        cpa16(sB + q * 16, b_p + q * 8);
    }
    cpa_commit();

    for (int c = 0; c < nc; c++) {
        const int s = c & 1;
        cpa_wait0();
        __syncthreads();
        if (c + 1 < nc) {
            const uint32_t so = (1 - s) * SM_STAGE;
            const __half* pa = a_p + (c + 1) * KC;
            const __half* pb = b_p + (c + 1) * KC;
#pragma unroll
            for (int q = 0; q < 4; q++) {
                cpa16(sA + so + q * 16, pa + q * 8);
                cpa16(sB + so + q * 16, pb + q * 8);
            }
            cpa_commit();
        }
        const char* pA = sm + s * SM_STAGE + SM_A;
        const char* pB = sm + s * SM_STAGE + SM_B;
#pragma unroll
        for (int ks = 0; ks < KC / 16; ks++) {
            uint32_t ah[2][4];
#pragma unroll
            for (int mi = 0; mi < 2; mi++) {
                int rbase = (wm0 + mi * 16 + g) * A_PITCH + ks * 32 + tg * 4;
                ah[mi][0] = *(const uint32_t*)(pA + rbase);
                ah[mi][1] = *(const uint32_t*)(pA + rbase + 8 * A_PITCH);
                ah[mi][2] = *(const uint32_t*)(pA + rbase + 16);
                ah[mi][3] = *(const uint32_t*)(pA + rbase + 8 * A_PITCH + 16);
            }
#pragma unroll
            for (int nj = 0; nj < 8; nj++) {
                int nb = (wn0 + nj * 8 + g) * A_PITCH + ks * 32 + tg * 4;
                uint32_t b0 = *(const uint32_t*)(pB + nb);
                uint32_t b1 = *(const uint32_t*)(pB + nb + 16);
#pragma unroll
                for (int mi = 0; mi < 2; mi++)
                    mma16816(acc[mi][nj], ah[mi][0], ah[mi][1], ah[mi][2], ah[mi][3], b0, b1);
            }
        }
    }
}

// ---------------- conversions (vectorized) ----------------
__global__ void k_cvt_x(const float* __restrict__ x) {
    size_t id = ((size_t)blockIdx.x * 256 + threadIdx.x) * 4;
    float4 v = *(const float4*)(x + id);
    __half2 a = __floats2half2_rn(v.x, v.y);
    __half2 b = __floats2half2_rn(v.z, v.w);
    *(__half2*)(g_x + id) = a;
    *(__half2*)(g_x + id + 2) = b;
}

// transpose-convert: src fp32 [K][N] (per-expert) -> dst fp16 [n'][K]
__device__ __forceinline__ void cvt_T_body(const float* __restrict__ s,
                                           __half* __restrict__ oh,
                                           int K, int N, int remap_half) {
    __shared__ float tile[32][33];
    int c0 = blockIdx.x * 32;
    int k0 = blockIdx.y * 32;
    int tx = threadIdx.x, ty = threadIdx.y;
#pragma unroll
    for (int i = 0; i < 4; i++) {
        int k = ty + i * 8;
        tile[k][tx] = s[(size_t)(k0 + k) * N + c0 + tx];
    }
    __syncthreads();
#pragma unroll
    for (int i = 0; i < 4; i++) {
        int cc = c0 + ty + i * 8;
        int n = remap_half ? (2 * (cc % remap_half) + cc / remap_half) : cc;
        oh[(size_t)n * K + k0 + tx] = __float2half_rn(tile[tx][ty + i * 8]);
    }
}

__global__ void k_cvt_gup(const float* __restrict__ gup) {
    int e = blockIdx.z;
    cvt_T_body(gup + (size_t)e * HDIM * 2 * IDIM,
               g_wgu + (size_t)e * 2 * IDIM * HDIM, HDIM, 2 * IDIM, IDIM);
}
__global__ void k_cvt_dwn(const float* __restrict__ dwn) {
    int e = blockIdx.z;
    cvt_T_body(dwn + (size_t)e * IDIM * HDIM,
               g_wdn + (size_t)e * HDIM * IDIM, IDIM, HDIM, 0);
}
__global__ void k_cvt_sharedgu(const float* __restrict__ gw, const float* __restrict__ uw) {
    size_t id = ((size_t)blockIdx.x * 256 + threadIdx.x) * 4;   // over I*H, 4-elem chunks
    int j = (int)(id / HDIM), k = (int)(id % HDIM);
    float4 gv = *(const float4*)(gw + id);
    float4 uv = *(const float4*)(uw + id);
    __half* dg = g_wsg + (size_t)(2 * j) * HDIM + k;
    __half* du = g_wsg + (size_t)(2 * j + 1) * HDIM + k;
    *(__half2*)(dg)     = __floats2half2_rn(gv.x, gv.y);
    *(__half2*)(dg + 2) = __floats2half2_rn(gv.z, gv.w);
    *(__half2*)(du)     = __floats2half2_rn(uv.x, uv.y);
    *(__half2*)(du + 2) = __floats2half2_rn(uv.z, uv.w);
}
__global__ void k_cvt_shareddn(const float* __restrict__ dw) {
    size_t id = ((size_t)blockIdx.x * 256 + threadIdx.x) * 4;   // over H*I
    float4 v = *(const float4*)(dw + id);
    *(__half2*)(g_wsd + id)     = __floats2half2_rn(v.x, v.y);
    *(__half2*)(g_wsd + id + 2) = __floats2half2_rn(v.z, v.w);
}

// ---------------- tiny control kernels ----------------
__global__ void k_init() { if (threadIdx.x < NE) g_cnt[threadIdx.x] = 0; }
__global__ void k_prefix() {
    if (threadIdx.x == 0) {
        int s = 0;
        for (int e = 0; e < NE; e++) { g_off[e] = s; s += g_cnt[e]; }
    }
    if (threadIdx.x < NE) g_cur[threadIdx.x] = 0;
}

// ---------------- router ----------------
__global__ __launch_bounds__(128) void k_router(const float* __restrict__ x,
                                                const float* __restrict__ rw,
                                                float* __restrict__ out_logits) {
    int warp = threadIdx.x >> 5, lane = threadIdx.x & 31;
    int t = blockIdx.x * 4 + warp;
    if (t >= TTOK) return;
    const float* xr = x + (size_t)t * HDIM;
    float acc[NE];
#pragma unroll
    for (int e = 0; e < NE; e++) acc[e] = 0.f;
    for (int i = lane; i < HDIM; i += 32) {
        float xv = xr[i];
#pragma unroll
        for (int e = 0; e < NE; e++) acc[e] = fmaf(xv, rw[e * HDIM + i], acc[e]);
    }
#pragma unroll
    for (int e = 0; e < NE; e++) {
#pragma unroll
        for (int o = 16; o > 0; o >>= 1) acc[e] += __shfl_xor_sync(0xFFFFFFFFu, acc[e], o);
    }
    if (lane == 0) {
        if (out_logits) {
#pragma unroll
            for (int e = 0; e < NE; e++) out_logits[(size_t)t * NE + e] = acc[e];
        }
        int e1 = 0; float v1 = acc[0];
#pragma unroll
        for (int e = 1; e < NE; e++) if (acc[e] > v1) { v1 = acc[e]; e1 = e; }
        int e2 = -1; float v2 = -1e30f;
#pragma unroll
        for (int e = 0; e < NE; e++) if (e != e1 && acc[e] > v2) { v2 = acc[e]; e2 = e; }
        float s1 = 1.f / (1.f + __expf(-v1));
        float s2 = 1.f / (1.f + __expf(-v2));
        g_tope[t * 2 + 0] = e1; g_tops[t * 2 + 0] = s1;
        g_tope[t * 2 + 1] = e2; g_tops[t * 2 + 1] = s2;
        atomicAdd(&g_cnt[e1], 1);
        atomicAdd(&g_cnt[e2], 1);
    }
}

// ---------------- scatter ----------------
__global__ __launch_bounds__(256) void k_scatter() {
    __shared__ int lcnt[NE], lbase[NE];
    int tid = threadIdx.x;
    if (tid < NE) lcnt[tid] = 0;
    __syncthreads();
    int t = blockIdx.x * 256 + tid;
    int e0 = g_tope[2 * t], e1 = g_tope[2 * t + 1];
    float s0 = g_tops[2 * t], s1 = g_tops[2 * t + 1];
    int p0 = atomicAdd(&lcnt[e0], 1);
    int p1 = atomicAdd(&lcnt[e1], 1);
    __syncthreads();
    if (tid < NE) lbase[tid] = atomicAdd(&g_cur[tid], lcnt[tid]);
    __syncthreads();
    int r0 = g_off[e0] + lbase[e0] + p0;
    int r1 = g_off[e1] + lbase[e1] + p1;
    g_row_tok[r0] = t; g_row_sc[r0] = s0; g_row_slot[r0] = 0;
    g_row_tok[r1] = t; g_row_sc[r1] = s1; g_row_slot[r1] = 1;
}

// ---------------- GEMM kernels ----------------
// L1: routed gate_up (2IDIM/128 x NE*32)
__global__ __launch_bounds__(256, 2) void tc_gu_routed() {
    int e = blockIdx.y >> 5, rt = blockIdx.y & 31;
    int cnt = g_cnt[e];
    int row0 = rt * 128;
    if (row0 >= cnt) return;
    int base = g_off[e];

    extern __shared__ char sm[];
    uint32_t sbu = smem_u32(sm);
    int t = threadIdx.x, rb = t >> 1, half = t & 1;
    int rr = base + min(row0 + rb, cnt - 1);
    const __half* ap = g_x + (size_t)g_row_tok[rr] * HDIM + half * 32;
    int n0 = blockIdx.x * 128;
    const __half* bp = g_wgu + (size_t)e * 2 * IDIM * HDIM + (size_t)(n0 + rb) * HDIM + half * 32;

    float acc[2][8][4];
#pragma unroll
    for (int a = 0; a < 2; a++)
#pragma unroll
        for (int b = 0; b < 8; b++)
#pragma unroll
            for (int q = 0; q < 4; q++) acc[a][b][q] = 0.f;

    gemm_core(ap, bp, HDIM, sm, sbu, acc);

    int lane = t & 31, wid = t >> 5, g = lane >> 2, tg = lane & 3;
    int wm0 = (wid >> 1) * 32;
    int jb = n0 / 2 + ((wid & 1) * 64) / 2 + tg;
#pragma unroll
    for (int mi = 0; mi < 2; mi++)
#pragma unroll
        for (int dq = 0; dq < 2; dq++) {
            int rl = wm0 + mi * 16 + g + dq * 8;
            if (row0 + rl < cnt) {
                int grow = base + row0 + rl;
                float sc = g_row_sc[grow];
                __half* dh = g_act + (size_t)grow * IDIM;
#pragma unroll
                for (int nj = 0; nj < 8; nj++) {
                    float v = silu_mul(sc * acc[mi][nj][dq * 2], sc * acc[mi][nj][dq * 2 + 1]);
                    dh[jb + nj * 4] = __float2half_rn(v);
                }
            }
        }
}

// L2 merged: routed down (y<256, x<8) + shared gate_up (y>=256, all x)
__global__ __launch_bounds__(256, 2) void tc_mid() {
    extern __shared__ char sm[];
    uint32_t sbu = smem_u32(sm);
    int t = threadIdx.x, rb = t >> 1, half = t & 1;
    int lane = t & 31, wid = t >> 5, g = lane >> 2, tg = lane & 3;
    int wm0 = (wid >> 1) * 32, wn0 = (wid & 1) * 64;

    float acc[2][8][4];
#pragma unroll
    for (int a = 0; a < 2; a++)
#pragma unroll
        for (int b = 0; b < 8; b++)
#pragma unroll
            for (int q = 0; q < 4; q++) acc[a][b][q] = 0.f;

    if (blockIdx.y < 256) {
        // ---- routed down ----
        if (blockIdx.x >= HDIM / 128) return;
        int e = blockIdx.y >> 5, rt = blockIdx.y & 31;
        int cnt = g_cnt[e];
        int row0 = rt * 128;
        if (row0 >= cnt) return;
        int base = g_off[e];
        const __half* ap = g_act + (size_t)(base + min(row0 + rb, cnt - 1)) * IDIM + half * 32;
        int n0 = blockIdx.x * 128;
        const __half* bp = g_wdn + (size_t)e * HDIM * IDIM + (size_t)(n0 + rb) * IDIM + half * 32;

        gemm_core(ap, bp, IDIM, sm, sbu, acc);

        int colb = n0 + wn0 + tg * 2;
#pragma unroll
        for (int mi = 0; mi < 2; mi++)
#pragma unroll
            for (int dq = 0; dq < 2; dq++) {
                int rl = wm0 + mi * 16 + g + dq * 8;
                if (row0 + rl < cnt) {
                    int grow = base + row0 + rl;
                    int tok = g_row_tok[grow], slot = g_row_slot[grow];
                    float* dst = g_partial[slot] + (size_t)tok * HDIM;
#pragma unroll
                    for (int nj = 0; nj < 8; nj++) {
                        float2 v = {acc[mi][nj][dq * 2], acc[mi][nj][dq * 2 + 1]};
                        *(float2*)&dst[colb + nj * 8] = v;
                    }
                }
            }
    } else {
        // ---- shared gate_up ----
        int row0 = (blockIdx.y - 256) * 128;
        int n0 = blockIdx.x * 128;
        const __half* ap = g_x + (size_t)(row0 + rb) * HDIM + half * 32;
        const __half* bp = g_wsg + (size_t)(n0 + rb) * HDIM + half * 32;

        gemm_core(ap, bp, HDIM, sm, sbu, acc);

        int jb = n0 / 2 + wn0 / 2 + tg;
#pragma unroll
        for (int mi = 0; mi < 2; mi++)
#pragma unroll
            for (int dq = 0; dq < 2; dq++) {
                int rl = wm0 + mi * 16 + g + dq * 8;
                __half* dh = g_acts + (size_t)(row0 + rl) * IDIM;
#pragma unroll
                for (int nj = 0; nj < 8; nj++) {
                    float v = silu_mul(acc[mi][nj][dq * 2], acc[mi][nj][dq * 2 + 1]);
                    dh[jb + nj * 4] = __float2half_rn(v);
                }
            }
    }
}

// L3: shared down + final add
__global__ __launch_bounds__(256, 2) void tc_dn_shared(float* __restrict__ out) {
    int row0 = blockIdx.y * 128;
    int n0 = blockIdx.x * 128;

    extern __shared__ char sm[];
    uint32_t sbu = smem_u32(sm);
    int t = threadIdx.x, rb = t >> 1, half = t & 1;
    const __half* ap = g_acts + (size_t)(row0 + rb) * IDIM + half * 32;
    const __half* bp = g_wsd + (size_t)(n0 + rb) * IDIM + half * 32;

    float acc[2][8][4];
#pragma unroll
    for (int a = 0; a < 2; a++)
#pragma unroll
        for (int b = 0; b < 8; b++)
#pragma unroll
            for (int q = 0; q < 4; q++) acc[a][b][q] = 0.f;

    gemm_core(ap, bp, IDIM, sm, sbu, acc);

    int lane = t & 31, wid = t >> 5, g = lane >> 2, tg = lane & 3;
    int wm0 = (wid >> 1) * 32, wn0 = (wid & 1) * 64;
    int colb = n0 + wn0 + tg * 2;
#pragma unroll
    for (int mi = 0; mi < 2; mi++)
#pragma unroll
        for (int dq = 0; dq < 2; dq++) {
            int row = row0 + wm0 + mi * 16 + g + dq * 8;
            size_t rbase = (size_t)row * HDIM;
#pragma unroll
            for (int nj = 0; nj < 8; nj++) {
                size_t idx = rbase + colb + nj * 8;
                float2 p0 = *(const float2*)&g_partial[0][idx];
                float2 p1 = *(const float2*)&g_partial[1][idx];
                float2 v;
                v.x = acc[mi][nj][dq * 2] + p0.x + p1.x;
                v.y = acc[mi][nj][dq * 2 + 1] + p0.y + p1.y;
                *(float2*)&out[idx] = v;
            }
        }
}

// ---------------- launch ----------------
extern "C" void kernel_launch(void* const* d_in, const int* in_sizes, int n_in,
                              void* d_out, int out_size) {
    const float* x     = (const float*)d_in[0];   // [T, H]
    const float* rw    = (const float*)d_in[1];   // [E, H]
    const float* gup   = (const float*)d_in[2];   // [E, H, 2I]
    const float* dwn   = (const float*)d_in[3];   // [E, I, H]
    const float* sgate = (const float*)d_in[4];   // [I, H]
    const float* sup   = (const float*)d_in[5];   // [I, H]
    const float* sdown = (const float*)d_in[6];   // [H, I]
    float* out = (float*)d_out;

    float* out_logits = nullptr;
    if (out_size >= TTOK * HDIM + TTOK * NE) out_logits = out + (size_t)TTOK * HDIM;

    cudaFuncSetAttribute(tc_gu_routed, cudaFuncAttributeMaxDynamicSharedMemorySize, SMEM_GEMM);
    cudaFuncSetAttribute(tc_mid,       cudaFuncAttributeMaxDynamicSharedMemorySize, SMEM_GEMM);
    cudaFuncSetAttribute(tc_dn_shared, cudaFuncAttributeMaxDynamicSharedMemorySize, SMEM_GEMM);

    k_init<<<1, 32>>>();
    k_router<<<TTOK / 4, 128>>>(x, rw, out_logits);
    k_prefix<<<1, 32>>>();
    k_scatter<<<TTOK / 256, 256>>>();

    // activation + weight conversions (fp16, mma-friendly layouts)
    k_cvt_x<<<(TTOK * HDIM) / 1024, 256>>>(x);
    k_cvt_gup<<<dim3(2 * IDIM / 32, HDIM / 32, NE), dim3(32, 8)>>>(gup);
    k_cvt_dwn<<<dim3(HDIM / 32, IDIM / 32, NE), dim3(32, 8)>>>(dwn);
    k_cvt_sharedgu<<<(IDIM * HDIM) / 1024, 256>>>(sgate, sup);
    k_cvt_shareddn<<<(HDIM * IDIM) / 1024, 256>>>(sdown);

    tc_gu_routed<<<dim3(2 * IDIM / 128, NE * 32), 256, SMEM_GEMM>>>();
    tc_mid<<<dim3(2 * IDIM / 128, 256 + TTOK / 128), 256, SMEM_GEMM>>>();
    tc_dn_shared<<<dim3(HDIM / 128, TTOK / 128), 256, SMEM_GEMM>>>(out);
}